// round 9
// baseline (speedup 1.0000x reference)
#include <cuda_runtime.h>
#include <stdint.h>

// ============================================================
// EGNN layer — single fused persistent kernel.
//   out = [h + segsum(m, dst) | x + segsum(cw * dir/len, dst)]
// Per-CTA weight fold into SMEM, out-init + grid barrier, then
// persistent tile loop with register-prefetched gather.
// edge_index is int32. Coord columns get split-tf32 correction
// on the 32 edge K-rows.
// ============================================================

#define ND 64
#define ED 32
#define HD 128
#define K1 160   // 2*ND + ED
#define N1 256   // HD (node) + HD (coord)
#define TILE 64
#define ASTRIDE 196  // 160 hi + 32 s_lo + 4 pad
#define NCTAS 148
#define NTHR 256

__device__ unsigned gBar;   // zero-init; monotonic across graph replays

__device__ __forceinline__ uint32_t f2t(float x) {
    uint32_t r;
    asm("cvt.rna.tf32.f32 %0, %1;" : "=r"(r) : "f"(x));
    return r;
}
__device__ __forceinline__ float silu_f(float v) {
    return v / (1.0f + __expf(-v));
}

// ------------------------------------------------------------
// SMEM layout (bytes) — identical to R7 passing kernel:
//   [0, 163840)        sW    : uint32[160*256] swizzled (n ^ ((k&3)<<3))
//   [163840, 180224)   sWlo  : uint32[32*128] swizzled (coord w_lo)
//   [180224, 230400)   union (phase-fenced by bar.sync):
//       A tile  uint32[64*196]  phases 1-2
//       sHidN   uint32[64*132]  phases 3-4
//       sM      float [64*68]   phases 5-6
//   [230400, 231424)   sP    : float[64*4]  coord dot partials
//   [231424, 231936)   sSrc int[64], sDst int[64]
// ------------------------------------------------------------
#define SW_OFF    0
#define SWLO_OFF  163840
#define UN_OFF    180224
#define SP_OFF    230400
#define META_OFF  231424
#define SMEM_TOTAL 231936

__global__ void __launch_bounds__(NTHR, 1)
egnn_fused(const float* __restrict__ h, const float* __restrict__ x,
           const int* __restrict__ ei, const float* __restrict__ ed,
           const float* __restrict__ We1, const float* __restrict__ be1,
           const float* __restrict__ We2, const float* __restrict__ be2,
           const float* __restrict__ Wn1, const float* __restrict__ bn1,
           const float* __restrict__ Wn2, const float* __restrict__ bn2,
           const float* __restrict__ Wc1, const float* __restrict__ bc1,
           const float* __restrict__ Wc2,
           float* __restrict__ out, int E, int NN)
{
    extern __shared__ char smem[];
    uint32_t* sW   = (uint32_t*)(smem + SW_OFF);
    uint32_t* sWlo = (uint32_t*)(smem + SWLO_OFF);
    uint32_t* sA   = (uint32_t*)(smem + UN_OFF);
    uint32_t* sHN  = (uint32_t*)(smem + UN_OFF);
    float*    sM   = (float*)   (smem + UN_OFF);
    float*    sP   = (float*)   (smem + SP_OFF);
    int*      sSrc = (int*)     (smem + META_OFF);
    int*      sDst = (int*)     (smem + META_OFF + 256);

    const int tid = threadIdx.x;
    const int w  = tid >> 5;
    const int l  = tid & 31;
    const int lg = l >> 2;
    const int lt = l & 3;
    float* outH = out;
    float* outX = out + (size_t)NN * ND;

    // ================= init out = [h | x] (grid-strided) =================
    {
        const float4* h4 = (const float4*)h;
        float4* o4 = (float4*)out;
        int nh4 = NN * (ND / 4);
        for (int i = blockIdx.x * NTHR + tid; i < nh4; i += gridDim.x * NTHR)
            o4[i] = h4[i];
        int nx = NN * 3;
        for (int i = blockIdx.x * NTHR + tid; i < nx; i += gridDim.x * NTHR)
            outX[i] = x[i];
    }

    // ================= per-CTA weight fold into SMEM =================
    for (int idx = tid; idx < K1 * N1; idx += NTHR) {
        int k = idx >> 8, n = idx & 255;
        const float* W = (n < HD) ? Wn1 : Wc1;
        int nn = (n < HD) ? n : n - HD;
        float v;
        if (k < 2 * ND) {
            v = W[k * HD + nn];
        } else {
            int i = k - 2 * ND;
            float s = 0.0f;
            for (int j = 0; j < ED; j++)
                s += We2[i * ED + j] * W[(2 * ND + j) * HD + nn];
            v = s;
        }
        uint32_t hb = f2t(v);
        sW[k * N1 + (n ^ ((k & 3) << 3))] = hb;
        if (k >= 2 * ND && n >= HD) {
            int kk = k - 2 * ND, n2 = n - HD;
            sWlo[kk * HD + (n2 ^ ((kk & 3) << 3))] = f2t(v - __uint_as_float(hb));
        }
    }

    // ---- persistent register preloads ----
    uint32_t bw2[16][2];                       // Wn2 B-fragments (tf32)
    #pragma unroll
    for (int ks = 0; ks < 16; ks++) {
        int kk = ks * 8 + lt;
        int nn = (w << 3) + lg;
        bw2[ks][0] = f2t(Wn2[kk * ND + nn]);
        bw2[ks][1] = f2t(Wn2[(kk + 4) * ND + nn]);
    }
    float bias1g[4][2];   // fused bias (includes be2 fold)
    float wc2r[4][2];
    #pragma unroll
    for (int nt = 0; nt < 4; nt++) {
        #pragma unroll
        for (int j = 0; j < 2; j++) {
            int col = (w << 5) + (nt << 3) + (lt << 1) + j;
            const float* W; int nn; float s;
            if (col < HD) { s = bn1[col];      W = Wn1; nn = col; }
            else          { s = bc1[col - HD]; W = Wc1; nn = col - HD; }
            for (int jj = 0; jj < ED; jj++)
                s += be2[jj] * W[(2 * ND + jj) * HD + nn];
            bias1g[nt][j] = s;
        }
        int col = (w << 5) + (nt << 3) + (lt << 1);
        wc2r[nt][0] = (w >= 4) ? Wc2[col - HD]     : 0.0f;
        wc2r[nt][1] = (w >= 4) ? Wc2[col - HD + 1] : 0.0f;
    }
    float bn2g0 = bn2[(w << 3) + (lt << 1)];
    float bn2g1 = bn2[(w << 3) + (lt << 1) + 1];

    const int t4 = tid & 3;
    const int em = tid >> 2;       // edge-in-tile this thread serves in ph1
    float we1r[2][4], be1r[2][4];  // edge-MLP first-layer slices
    #pragma unroll
    for (int gg = 0; gg < 2; gg++)
        #pragma unroll
        for (int j = 0; j < 4; j++) {
            int i = (t4 << 2) + (gg << 4) + j;
            we1r[gg][j] = We1[i];
            be1r[gg][j] = be1[i];
        }

    // ================= grid barrier (monotonic epochs) =================
    __threadfence();
    __syncthreads();
    if (tid == 0) {
        unsigned ticket = atomicAdd(&gBar, 1u);
        unsigned target = (ticket / (unsigned)gridDim.x + 1u) * (unsigned)gridDim.x;
        unsigned v;
        do {
            asm volatile("ld.global.acquire.gpu.u32 %0, [%1];" : "=r"(v) : "l"(&gBar));
        } while (v < target);
    }
    __syncthreads();

    // ================= gather prefetch state =================
    int   pf_src = -1, pf_dst = -1;
    float pf_dist = 0.0f;
    float4 ps[4], pd4[4];

    auto do_prefetch = [&](int tt) {
        int e = tt * TILE + em;
        pf_src = -1; pf_dst = -1;
        if (e < E) {
            pf_src  = ei[e];
            pf_dst  = ei[E + e];
            pf_dist = ed[e];
            const float4* rs = (const float4*)(h + (size_t)pf_src * ND);
            const float4* rd = (const float4*)(h + (size_t)pf_dst * ND);
            #pragma unroll
            for (int g = 0; g < 4; g++) {
                ps[g]  = rs[t4 + (g << 2)];
                pd4[g] = rd[t4 + (g << 2)];
            }
        }
    };

    const int nTiles = (E + TILE - 1) / TILE;
    int t = blockIdx.x;
    if (t < nTiles) do_prefetch(t);

    for (; t < nTiles; t += gridDim.x) {
        const int base = t * TILE;

        // ================= phase 1: consume prefetch -> A tile =============
        {
            int e = base + em;
            uint32_t* Arow = sA + em * ASTRIDE;
            if (e < E) {
                if (t4 == 0) { sSrc[em] = pf_src; sDst[em] = pf_dst; }
                #pragma unroll
                for (int g = 0; g < 4; g++) {
                    float4 v = ps[g];
                    uint4 u; u.x = f2t(v.x); u.y = f2t(v.y); u.z = f2t(v.z); u.w = f2t(v.w);
                    *(uint4*)&Arow[(t4 + (g << 2)) << 2] = u;
                    float4 v2 = pd4[g];
                    uint4 u2; u2.x = f2t(v2.x); u2.y = f2t(v2.y); u2.z = f2t(v2.z); u2.w = f2t(v2.w);
                    *(uint4*)&Arow[(t4 + 16 + (g << 2)) << 2] = u2;
                }
                #pragma unroll
                for (int gg = 0; gg < 2; gg++) {
                    int i0 = (t4 << 2) + (gg << 4);
                    uint4 hi, lo;
                    float s;
                    s = silu_f(pf_dist * we1r[gg][0] + be1r[gg][0]);
                    hi.x = f2t(s); lo.x = f2t(s - __uint_as_float(hi.x));
                    s = silu_f(pf_dist * we1r[gg][1] + be1r[gg][1]);
                    hi.y = f2t(s); lo.y = f2t(s - __uint_as_float(hi.y));
                    s = silu_f(pf_dist * we1r[gg][2] + be1r[gg][2]);
                    hi.z = f2t(s); lo.z = f2t(s - __uint_as_float(hi.z));
                    s = silu_f(pf_dist * we1r[gg][3] + be1r[gg][3]);
                    hi.w = f2t(s); lo.w = f2t(s - __uint_as_float(hi.w));
                    *(uint4*)&Arow[128 + i0] = hi;
                    *(uint4*)&Arow[160 + i0] = lo;
                }
            } else {
                if (t4 == 0) { sSrc[em] = 0; sDst[em] = -1; }
                uint4 z; z.x = z.y = z.z = z.w = 0;
                #pragma unroll
                for (int g = 0; g < 4; g++) {
                    *(uint4*)&Arow[(t4 + (g << 2)) << 2] = z;
                    *(uint4*)&Arow[(t4 + 16 + (g << 2)) << 2] = z;
                }
                #pragma unroll
                for (int gg = 0; gg < 2; gg++) {
                    int i0 = (t4 << 2) + (gg << 4);
                    *(uint4*)&Arow[128 + i0] = z;
                    *(uint4*)&Arow[160 + i0] = z;
                }
            }
        }
        __syncthreads();

        // ================= phase 2: GEMM1 (64x256x160 + coord corr) =========
        float c1[4][4][4];
        #pragma unroll
        for (int a = 0; a < 4; a++)
            #pragma unroll
            for (int b = 0; b < 4; b++)
                #pragma unroll
                for (int r = 0; r < 4; r++) c1[a][b][r] = 0.0f;

        const int sw = lt << 3;
        #pragma unroll 2
        for (int ks = 0; ks < 20; ks++) {
            int k0 = ks << 3;
            uint32_t af[4][4];
            #pragma unroll
            for (int mt = 0; mt < 4; mt++) {
                int ba = ((mt << 4) + lg) * ASTRIDE + k0 + lt;
                af[mt][0] = sA[ba];
                af[mt][1] = sA[ba + 8 * ASTRIDE];
                af[mt][2] = sA[ba + 4];
                af[mt][3] = sA[ba + 8 * ASTRIDE + 4];
            }
            uint32_t bf[4][2];
            int kb = (k0 + lt) * N1;
            #pragma unroll
            for (int nt = 0; nt < 4; nt++) {
                int cc = ((w << 5) + (nt << 3) + lg) ^ sw;
                bf[nt][0] = sW[kb + cc];
                bf[nt][1] = sW[kb + 4 * N1 + cc];
            }
            #pragma unroll
            for (int mt = 0; mt < 4; mt++)
                #pragma unroll
                for (int nt = 0; nt < 4; nt++)
                    asm volatile(
                        "mma.sync.aligned.m16n8k8.row.col.f32.tf32.tf32.f32 "
                        "{%0,%1,%2,%3}, {%4,%5,%6,%7}, {%8,%9}, {%0,%1,%2,%3};"
                        : "+f"(c1[mt][nt][0]), "+f"(c1[mt][nt][1]),
                          "+f"(c1[mt][nt][2]), "+f"(c1[mt][nt][3])
                        : "r"(af[mt][0]), "r"(af[mt][1]), "r"(af[mt][2]), "r"(af[mt][3]),
                          "r"(bf[nt][0]), "r"(bf[nt][1]));
        }

        if (w >= 4) {
            // correction 1: s_lo * w_hi
            #pragma unroll
            for (int ks = 0; ks < 4; ks++) {
                int k0a = 160 + (ks << 3);
                int k0b = 128 + (ks << 3);
                uint32_t af[4][4];
                #pragma unroll
                for (int mt = 0; mt < 4; mt++) {
                    int ba = ((mt << 4) + lg) * ASTRIDE + k0a + lt;
                    af[mt][0] = sA[ba];
                    af[mt][1] = sA[ba + 8 * ASTRIDE];
                    af[mt][2] = sA[ba + 4];
                    af[mt][3] = sA[ba + 8 * ASTRIDE + 4];
                }
                uint32_t bf[4][2];
                int kb = (k0b + lt) * N1;
                #pragma unroll
                for (int nt = 0; nt < 4; nt++) {
                    int cc = ((w << 5) + (nt << 3) + lg) ^ sw;
                    bf[nt][0] = sW[kb + cc];
                    bf[nt][1] = sW[kb + 4 * N1 + cc];
                }
                #pragma unroll
                for (int mt = 0; mt < 4; mt++)
                    #pragma unroll
                    for (int nt = 0; nt < 4; nt++)
                        asm volatile(
                            "mma.sync.aligned.m16n8k8.row.col.f32.tf32.tf32.f32 "
                            "{%0,%1,%2,%3}, {%4,%5,%6,%7}, {%8,%9}, {%0,%1,%2,%3};"
                            : "+f"(c1[mt][nt][0]), "+f"(c1[mt][nt][1]),
                              "+f"(c1[mt][nt][2]), "+f"(c1[mt][nt][3])
                            : "r"(af[mt][0]), "r"(af[mt][1]), "r"(af[mt][2]), "r"(af[mt][3]),
                              "r"(bf[nt][0]), "r"(bf[nt][1]));
            }
            // correction 2: s_hi * w_lo
            #pragma unroll
            for (int ks = 0; ks < 4; ks++) {
                int k0a = 128 + (ks << 3);
                int k0b = ks << 3;
                uint32_t af[4][4];
                #pragma unroll
                for (int mt = 0; mt < 4; mt++) {
                    int ba = ((mt << 4) + lg) * ASTRIDE + k0a + lt;
                    af[mt][0] = sA[ba];
                    af[mt][1] = sA[ba + 8 * ASTRIDE];
                    af[mt][2] = sA[ba + 4];
                    af[mt][3] = sA[ba + 8 * ASTRIDE + 4];
                }
                uint32_t bf[4][2];
                int kb = (k0b + lt) * HD;
                #pragma unroll
                for (int nt = 0; nt < 4; nt++) {
                    int cc = (((w - 4) << 5) + (nt << 3) + lg) ^ sw;
                    bf[nt][0] = sWlo[kb + cc];
                    bf[nt][1] = sWlo[kb + 4 * HD + cc];
                }
                #pragma unroll
                for (int mt = 0; mt < 4; mt++)
                    #pragma unroll
                    for (int nt = 0; nt < 4; nt++)
                        asm volatile(
                            "mma.sync.aligned.m16n8k8.row.col.f32.tf32.tf32.f32 "
                            "{%0,%1,%2,%3}, {%4,%5,%6,%7}, {%8,%9}, {%0,%1,%2,%3};"
                            : "+f"(c1[mt][nt][0]), "+f"(c1[mt][nt][1]),
                              "+f"(c1[mt][nt][2]), "+f"(c1[mt][nt][3])
                            : "r"(af[mt][0]), "r"(af[mt][1]), "r"(af[mt][2]), "r"(af[mt][3]),
                              "r"(bf[nt][0]), "r"(bf[nt][1]));
            }
        }
        __syncthreads();  // all warps done reading sA

        // ====== phase 3: bias + SiLU; node->sHN(tf32), coord->dot partials ===
        if (w < 4) {
            #pragma unroll
            for (int mt = 0; mt < 4; mt++)
                #pragma unroll
                for (int nt = 0; nt < 4; nt++)
                    #pragma unroll
                    for (int r = 0; r < 4; r++) {
                        int row = (mt << 4) + lg + ((r >= 2) ? 8 : 0);
                        int col = (w << 5) + (nt << 3) + (lt << 1) + (r & 1);
                        float v = silu_f(c1[mt][nt][r] + bias1g[nt][r & 1]);
                        sHN[row * 132 + col] = f2t(v);
                    }
        } else {
            float part[4][2];
            #pragma unroll
            for (int mt = 0; mt < 4; mt++) { part[mt][0] = 0.0f; part[mt][1] = 0.0f; }
            #pragma unroll
            for (int mt = 0; mt < 4; mt++)
                #pragma unroll
                for (int nt = 0; nt < 4; nt++)
                    #pragma unroll
                    for (int r = 0; r < 4; r++) {
                        float v = silu_f(c1[mt][nt][r] + bias1g[nt][r & 1]);
                        part[mt][r >> 1] += v * wc2r[nt][r & 1];
                    }
            #pragma unroll
            for (int mt = 0; mt < 4; mt++)
                #pragma unroll
                for (int rh = 0; rh < 2; rh++) {
                    float p = part[mt][rh];
                    p += __shfl_xor_sync(0xffffffffu, p, 1);
                    p += __shfl_xor_sync(0xffffffffu, p, 2);
                    if (lt == 0) {
                        int row = (mt << 4) + lg + (rh << 3);
                        sP[row * 4 + (w - 4)] = p;
                    }
                }
        }
        __syncthreads();

        // ================= phase 4: GEMM2 (64x64x128, tf32) =================
        float c2[4][4];
        #pragma unroll
        for (int a = 0; a < 4; a++)
            #pragma unroll
            for (int r = 0; r < 4; r++) c2[a][r] = 0.0f;

        #pragma unroll 4
        for (int ks = 0; ks < 16; ks++) {
            int k0 = ks << 3;
            #pragma unroll
            for (int mt = 0; mt < 4; mt++) {
                int ba = ((mt << 4) + lg) * 132 + k0 + lt;
                uint32_t a0 = sHN[ba];
                uint32_t a1 = sHN[ba + 8 * 132];
                uint32_t a2 = sHN[ba + 4];
                uint32_t a3 = sHN[ba + 8 * 132 + 4];
                asm volatile(
                    "mma.sync.aligned.m16n8k8.row.col.f32.tf32.tf32.f32 "
                    "{%0,%1,%2,%3}, {%4,%5,%6,%7}, {%8,%9}, {%0,%1,%2,%3};"
                    : "+f"(c2[mt][0]), "+f"(c2[mt][1]), "+f"(c2[mt][2]), "+f"(c2[mt][3])
                    : "r"(a0), "r"(a1), "r"(a2), "r"(a3),
                      "r"(bw2[ks][0]), "r"(bw2[ks][1]));
            }
        }
        __syncthreads();  // sHN reads done before sM overwrites

        // ---- prefetch next tile's gather (c1 dead; covers phases 5-6) ----
        do_prefetch(t + gridDim.x);

        // ================= phase 5: stage m; coord epilogue =================
        #pragma unroll
        for (int mt = 0; mt < 4; mt++)
            #pragma unroll
            for (int r = 0; r < 4; r++) {
                int row = (mt << 4) + lg + ((r >= 2) ? 8 : 0);
                int col = (w << 3) + (lt << 1) + (r & 1);
                sM[row * 68 + col] = c2[mt][r] + ((r & 1) ? bn2g1 : bn2g0);
            }

        if (tid < TILE) {
            int m = tid;
            int dst = sDst[m];
            if (dst >= 0) {
                float cw = sP[m * 4] + sP[m * 4 + 1] + sP[m * 4 + 2] + sP[m * 4 + 3];
                int src = sSrc[m];
                float dx = x[src * 3]     - x[dst * 3];
                float dy = x[src * 3 + 1] - x[dst * 3 + 1];
                float dz = x[src * 3 + 2] - x[dst * 3 + 2];
                float len = sqrtf(dx * dx + dy * dy + dz * dz);
                len = fmaxf(len, 1e-8f);
                float s = cw / len;
                float* xo = outX + (size_t)dst * 3;
                asm volatile("red.global.add.f32 [%0], %1;" :: "l"(xo),     "f"(s * dx) : "memory");
                asm volatile("red.global.add.f32 [%0], %1;" :: "l"(xo + 1), "f"(s * dy) : "memory");
                asm volatile("red.global.add.f32 [%0], %1;" :: "l"(xo + 2), "f"(s * dz) : "memory");
            }
        }
        __syncthreads();  // sM visible to all

        // ================= phase 6: scatter h messages =================
        for (int i = tid; i < TILE * 16; i += NTHR) {
            int m = i >> 4, q = i & 15;
            int dst = sDst[m];
            if (dst >= 0) {
                float4 v = *(const float4*)(sM + m * 68 + (q << 2));
                float* ho = outH + (size_t)dst * ND + (q << 2);
                asm volatile("red.global.add.v4.f32 [%0], {%1,%2,%3,%4};"
                             :: "l"(ho), "f"(v.x), "f"(v.y), "f"(v.z), "f"(v.w) : "memory");
            }
        }
        __syncthreads();  // sM / sP reads done before next tile
    }
}

// ------------------------------------------------------------
extern "C" void kernel_launch(void* const* d_in, const int* in_sizes, int n_in,
                              void* d_out, int out_size)
{
    const float* h   = (const float*)d_in[0];
    const float* x   = (const float*)d_in[1];
    const int*   ei  = (const int*)d_in[2];      // int32 (JAX x64 disabled)
    const float* ed  = (const float*)d_in[3];
    const float* We1 = (const float*)d_in[4];
    const float* be1 = (const float*)d_in[5];
    const float* We2 = (const float*)d_in[6];
    const float* be2 = (const float*)d_in[7];
    const float* Wn1 = (const float*)d_in[8];
    const float* bn1 = (const float*)d_in[9];
    const float* Wn2 = (const float*)d_in[10];
    const float* bn2 = (const float*)d_in[11];
    const float* Wc1 = (const float*)d_in[12];
    const float* bc1 = (const float*)d_in[13];
    const float* Wc2 = (const float*)d_in[14];
    float* out = (float*)d_out;

    int E  = in_sizes[3];        // edge_dist element count
    int NN = in_sizes[0] / ND;   // nodes

    cudaFuncSetAttribute(egnn_fused, cudaFuncAttributeMaxDynamicSharedMemorySize, SMEM_TOTAL);

    egnn_fused<<<NCTAS, NTHR, SMEM_TOTAL>>>(h, x, ei, ed,
                                            We1, be1, We2, be2,
                                            Wn1, bn1, Wn2, bn2,
                                            Wc1, bc1, Wc2,
                                            out, E, NN);
}

// round 10
// speedup vs baseline: 1.5211x; 1.5211x over previous
#include <cuda_runtime.h>
#include <stdint.h>

// ============================================================
// EGNN layer — single fused persistent kernel.
//   out = [h + segsum(m, dst) | x + segsum(cw * dir/len, dst)]
// Per-CTA weight fold into SMEM, out-init + grid barrier, then
// persistent tile loop. Index/dist-only prefetch (low reg cost);
// h-row gather issued en-bloc at phase 1 (L2 hits).
// edge_index is int32. Coord columns get split-tf32 correction
// on the 32 edge K-rows.
// ============================================================

#define ND 64
#define ED 32
#define HD 128
#define K1 160   // 2*ND + ED
#define N1 256   // HD (node) + HD (coord)
#define TILE 64
#define ASTRIDE 196  // 160 hi + 32 s_lo + 4 pad
#define NCTAS 148
#define NTHR 256

__device__ unsigned gBar;   // zero-init; monotonic across graph replays

__device__ __forceinline__ uint32_t f2t(float x) {
    uint32_t r;
    asm("cvt.rna.tf32.f32 %0, %1;" : "=r"(r) : "f"(x));
    return r;
}
__device__ __forceinline__ float silu_f(float v) {
    return v / (1.0f + __expf(-v));
}

// ------------------------------------------------------------
// SMEM layout (bytes):
//   [0, 163840)        sW    : uint32[160*256] swizzled (n ^ ((k&3)<<3))
//   [163840, 180224)   sWlo  : uint32[32*128] swizzled (coord w_lo)
//   [180224, 230400)   union (phase-fenced by bar.sync):
//       A tile  uint32[64*196]  phases 1-2
//       sHidN   uint32[64*132]  phases 3-4
//       sM      float [64*68]   phases 5-6
//   [230400, 231424)   sP    : float[64*4]  coord dot partials
//   [231424, 231936)   sSrc int[64], sDst int[64]
// ------------------------------------------------------------
#define SW_OFF    0
#define SWLO_OFF  163840
#define UN_OFF    180224
#define SP_OFF    230400
#define META_OFF  231424
#define SMEM_TOTAL 231936

__global__ void __launch_bounds__(NTHR, 1)
egnn_fused(const float* __restrict__ h, const float* __restrict__ x,
           const int* __restrict__ ei, const float* __restrict__ ed,
           const float* __restrict__ We1, const float* __restrict__ be1,
           const float* __restrict__ We2, const float* __restrict__ be2,
           const float* __restrict__ Wn1, const float* __restrict__ bn1,
           const float* __restrict__ Wn2, const float* __restrict__ bn2,
           const float* __restrict__ Wc1, const float* __restrict__ bc1,
           const float* __restrict__ Wc2,
           float* __restrict__ out, int E, int NN)
{
    extern __shared__ char smem[];
    uint32_t* sW   = (uint32_t*)(smem + SW_OFF);
    uint32_t* sWlo = (uint32_t*)(smem + SWLO_OFF);
    uint32_t* sA   = (uint32_t*)(smem + UN_OFF);
    uint32_t* sHN  = (uint32_t*)(smem + UN_OFF);
    float*    sM   = (float*)   (smem + UN_OFF);
    float*    sP   = (float*)   (smem + SP_OFF);
    int*      sSrc = (int*)     (smem + META_OFF);
    int*      sDst = (int*)     (smem + META_OFF + 256);

    const int tid = threadIdx.x;
    const int w  = tid >> 5;
    const int l  = tid & 31;
    const int lg = l >> 2;
    const int lt = l & 3;
    float* outH = out;
    float* outX = out + (size_t)NN * ND;

    // ================= init out = [h | x] (grid-strided) =================
    {
        const float4* h4 = (const float4*)h;
        float4* o4 = (float4*)out;
        int nh4 = NN * (ND / 4);
        for (int i = blockIdx.x * NTHR + tid; i < nh4; i += gridDim.x * NTHR)
            o4[i] = h4[i];
        int nx = NN * 3;
        for (int i = blockIdx.x * NTHR + tid; i < nx; i += gridDim.x * NTHR)
            outX[i] = x[i];
    }

    // ================= per-CTA weight fold into SMEM =================
    for (int idx = tid; idx < K1 * N1; idx += NTHR) {
        int k = idx >> 8, n = idx & 255;
        const float* W = (n < HD) ? Wn1 : Wc1;
        int nn = (n < HD) ? n : n - HD;
        float v;
        if (k < 2 * ND) {
            v = W[k * HD + nn];
        } else {
            int i = k - 2 * ND;
            float s = 0.0f;
            for (int j = 0; j < ED; j++)
                s += We2[i * ED + j] * W[(2 * ND + j) * HD + nn];
            v = s;
        }
        uint32_t hb = f2t(v);
        sW[k * N1 + (n ^ ((k & 3) << 3))] = hb;
        if (k >= 2 * ND && n >= HD) {
            int kk = k - 2 * ND, n2 = n - HD;
            sWlo[kk * HD + (n2 ^ ((kk & 3) << 3))] = f2t(v - __uint_as_float(hb));
        }
    }

    // ---- persistent register preloads ----
    uint32_t bw2[16][2];                       // Wn2 B-fragments (tf32)
    #pragma unroll
    for (int ks = 0; ks < 16; ks++) {
        int kk = ks * 8 + lt;
        int nn = (w << 3) + lg;
        bw2[ks][0] = f2t(Wn2[kk * ND + nn]);
        bw2[ks][1] = f2t(Wn2[(kk + 4) * ND + nn]);
    }
    float bias1g[4][2];   // fused bias (includes be2 fold)
    float wc2r[4][2];
    #pragma unroll
    for (int nt = 0; nt < 4; nt++) {
        #pragma unroll
        for (int j = 0; j < 2; j++) {
            int col = (w << 5) + (nt << 3) + (lt << 1) + j;
            const float* W; int nn; float s;
            if (col < HD) { s = bn1[col];      W = Wn1; nn = col; }
            else          { s = bc1[col - HD]; W = Wc1; nn = col - HD; }
            for (int jj = 0; jj < ED; jj++)
                s += be2[jj] * W[(2 * ND + jj) * HD + nn];
            bias1g[nt][j] = s;
        }
        int col = (w << 5) + (nt << 3) + (lt << 1);
        wc2r[nt][0] = (w >= 4) ? Wc2[col - HD]     : 0.0f;
        wc2r[nt][1] = (w >= 4) ? Wc2[col - HD + 1] : 0.0f;
    }
    float bn2g0 = bn2[(w << 3) + (lt << 1)];
    float bn2g1 = bn2[(w << 3) + (lt << 1) + 1];

    const int t4 = tid & 3;
    const int em = tid >> 2;       // edge-in-tile this thread serves in ph1
    float we1r[2][4], be1r[2][4];  // edge-MLP first-layer slices
    #pragma unroll
    for (int gg = 0; gg < 2; gg++)
        #pragma unroll
        for (int j = 0; j < 4; j++) {
            int i = (t4 << 2) + (gg << 4) + j;
            we1r[gg][j] = We1[i];
            be1r[gg][j] = be1[i];
        }

    // ================= grid barrier (monotonic epochs) =================
    __threadfence();
    __syncthreads();
    if (tid == 0) {
        unsigned ticket = atomicAdd(&gBar, 1u);
        unsigned target = (ticket / (unsigned)gridDim.x + 1u) * (unsigned)gridDim.x;
        unsigned v;
        do {
            asm volatile("ld.global.acquire.gpu.u32 %0, [%1];" : "=r"(v) : "l"(&gBar));
        } while (v < target);
    }
    __syncthreads();

    // ========= lightweight prefetch: indices + dist only (3 regs) =========
    int   pf_src = -1, pf_dst = -1;
    float pf_dist = 0.0f;

    auto pf_idx = [&](int tt) {
        int e = tt * TILE + em;
        pf_src = -1; pf_dst = -1;
        if (e < E) {
            pf_src  = ei[e];
            pf_dst  = ei[E + e];
            pf_dist = ed[e];
        }
    };

    const int nTiles = (E + TILE - 1) / TILE;
    int t = blockIdx.x;
    if (t < nTiles) pf_idx(t);

    for (; t < nTiles; t += gridDim.x) {
        // ================= phase 1: gather -> A tile =================
        {
            uint32_t* Arow = sA + em * ASTRIDE;
            if (pf_dst >= 0) {
                if (t4 == 0) { sSrc[em] = pf_src; sDst[em] = pf_dst; }
                const float4* rs = (const float4*)(h + (size_t)pf_src * ND);
                const float4* rd = (const float4*)(h + (size_t)pf_dst * ND);
                float4 vs0 = rs[t4];      float4 vs1 = rs[t4 + 4];
                float4 vs2 = rs[t4 + 8];  float4 vs3 = rs[t4 + 12];
                float4 vd0 = rd[t4];      float4 vd1 = rd[t4 + 4];
                float4 vd2 = rd[t4 + 8];  float4 vd3 = rd[t4 + 12];
                uint4 u;
                #define CVT_ST(v, off) \
                    u.x = f2t(v.x); u.y = f2t(v.y); u.z = f2t(v.z); u.w = f2t(v.w); \
                    *(uint4*)&Arow[off] = u;
                CVT_ST(vs0, (t4)      << 2)  CVT_ST(vs1, (t4 + 4)  << 2)
                CVT_ST(vs2, (t4 + 8)  << 2)  CVT_ST(vs3, (t4 + 12) << 2)
                CVT_ST(vd0, (t4 + 16) << 2)  CVT_ST(vd1, (t4 + 20) << 2)
                CVT_ST(vd2, (t4 + 24) << 2)  CVT_ST(vd3, (t4 + 28) << 2)
                #undef CVT_ST
                #pragma unroll
                for (int gg = 0; gg < 2; gg++) {
                    int i0 = (t4 << 2) + (gg << 4);
                    uint4 hi, lo;
                    float s;
                    s = silu_f(pf_dist * we1r[gg][0] + be1r[gg][0]);
                    hi.x = f2t(s); lo.x = f2t(s - __uint_as_float(hi.x));
                    s = silu_f(pf_dist * we1r[gg][1] + be1r[gg][1]);
                    hi.y = f2t(s); lo.y = f2t(s - __uint_as_float(hi.y));
                    s = silu_f(pf_dist * we1r[gg][2] + be1r[gg][2]);
                    hi.z = f2t(s); lo.z = f2t(s - __uint_as_float(hi.z));
                    s = silu_f(pf_dist * we1r[gg][3] + be1r[gg][3]);
                    hi.w = f2t(s); lo.w = f2t(s - __uint_as_float(hi.w));
                    *(uint4*)&Arow[128 + i0] = hi;
                    *(uint4*)&Arow[160 + i0] = lo;
                }
            } else {
                if (t4 == 0) { sSrc[em] = 0; sDst[em] = -1; }
                uint4 z; z.x = z.y = z.z = z.w = 0;
                #pragma unroll
                for (int g = 0; g < 4; g++) {
                    *(uint4*)&Arow[(t4 + (g << 2)) << 2] = z;
                    *(uint4*)&Arow[(t4 + 16 + (g << 2)) << 2] = z;
                }
                #pragma unroll
                for (int gg = 0; gg < 2; gg++) {
                    int i0 = (t4 << 2) + (gg << 4);
                    *(uint4*)&Arow[128 + i0] = z;
                    *(uint4*)&Arow[160 + i0] = z;
                }
            }
        }
        __syncthreads();

        // ================= phase 2: GEMM1 (64x256x160 + coord corr) =========
        float c1[4][4][4];
        #pragma unroll
        for (int a = 0; a < 4; a++)
            #pragma unroll
            for (int b = 0; b < 4; b++)
                #pragma unroll
                for (int r = 0; r < 4; r++) c1[a][b][r] = 0.0f;

        const int sw = lt << 3;
        #pragma unroll 2
        for (int ks = 0; ks < 20; ks++) {
            int k0 = ks << 3;
            uint32_t af[4][4];
            #pragma unroll
            for (int mt = 0; mt < 4; mt++) {
                int ba = ((mt << 4) + lg) * ASTRIDE + k0 + lt;
                af[mt][0] = sA[ba];
                af[mt][1] = sA[ba + 8 * ASTRIDE];
                af[mt][2] = sA[ba + 4];
                af[mt][3] = sA[ba + 8 * ASTRIDE + 4];
            }
            uint32_t bf[4][2];
            int kb = (k0 + lt) * N1;
            #pragma unroll
            for (int nt = 0; nt < 4; nt++) {
                int cc = ((w << 5) + (nt << 3) + lg) ^ sw;
                bf[nt][0] = sW[kb + cc];
                bf[nt][1] = sW[kb + 4 * N1 + cc];
            }
            #pragma unroll
            for (int mt = 0; mt < 4; mt++)
                #pragma unroll
                for (int nt = 0; nt < 4; nt++)
                    asm volatile(
                        "mma.sync.aligned.m16n8k8.row.col.f32.tf32.tf32.f32 "
                        "{%0,%1,%2,%3}, {%4,%5,%6,%7}, {%8,%9}, {%0,%1,%2,%3};"
                        : "+f"(c1[mt][nt][0]), "+f"(c1[mt][nt][1]),
                          "+f"(c1[mt][nt][2]), "+f"(c1[mt][nt][3])
                        : "r"(af[mt][0]), "r"(af[mt][1]), "r"(af[mt][2]), "r"(af[mt][3]),
                          "r"(bf[nt][0]), "r"(bf[nt][1]));
        }

        if (w >= 4) {
            // correction 1: s_lo * w_hi
            #pragma unroll
            for (int ks = 0; ks < 4; ks++) {
                int k0a = 160 + (ks << 3);
                int k0b = 128 + (ks << 3);
                uint32_t af[4][4];
                #pragma unroll
                for (int mt = 0; mt < 4; mt++) {
                    int ba = ((mt << 4) + lg) * ASTRIDE + k0a + lt;
                    af[mt][0] = sA[ba];
                    af[mt][1] = sA[ba + 8 * ASTRIDE];
                    af[mt][2] = sA[ba + 4];
                    af[mt][3] = sA[ba + 8 * ASTRIDE + 4];
                }
                uint32_t bf[4][2];
                int kb = (k0b + lt) * N1;
                #pragma unroll
                for (int nt = 0; nt < 4; nt++) {
                    int cc = ((w << 5) + (nt << 3) + lg) ^ sw;
                    bf[nt][0] = sW[kb + cc];
                    bf[nt][1] = sW[kb + 4 * N1 + cc];
                }
                #pragma unroll
                for (int mt = 0; mt < 4; mt++)
                    #pragma unroll
                    for (int nt = 0; nt < 4; nt++)
                        asm volatile(
                            "mma.sync.aligned.m16n8k8.row.col.f32.tf32.tf32.f32 "
                            "{%0,%1,%2,%3}, {%4,%5,%6,%7}, {%8,%9}, {%0,%1,%2,%3};"
                            : "+f"(c1[mt][nt][0]), "+f"(c1[mt][nt][1]),
                              "+f"(c1[mt][nt][2]), "+f"(c1[mt][nt][3])
                            : "r"(af[mt][0]), "r"(af[mt][1]), "r"(af[mt][2]), "r"(af[mt][3]),
                              "r"(bf[nt][0]), "r"(bf[nt][1]));
            }
            // correction 2: s_hi * w_lo
            #pragma unroll
            for (int ks = 0; ks < 4; ks++) {
                int k0a = 128 + (ks << 3);
                int k0b = ks << 3;
                uint32_t af[4][4];
                #pragma unroll
                for (int mt = 0; mt < 4; mt++) {
                    int ba = ((mt << 4) + lg) * ASTRIDE + k0a + lt;
                    af[mt][0] = sA[ba];
                    af[mt][1] = sA[ba + 8 * ASTRIDE];
                    af[mt][2] = sA[ba + 4];
                    af[mt][3] = sA[ba + 8 * ASTRIDE + 4];
                }
                uint32_t bf[4][2];
                int kb = (k0b + lt) * HD;
                #pragma unroll
                for (int nt = 0; nt < 4; nt++) {
                    int cc = (((w - 4) << 5) + (nt << 3) + lg) ^ sw;
                    bf[nt][0] = sWlo[kb + cc];
                    bf[nt][1] = sWlo[kb + 4 * HD + cc];
                }
                #pragma unroll
                for (int mt = 0; mt < 4; mt++)
                    #pragma unroll
                    for (int nt = 0; nt < 4; nt++)
                        asm volatile(
                            "mma.sync.aligned.m16n8k8.row.col.f32.tf32.tf32.f32 "
                            "{%0,%1,%2,%3}, {%4,%5,%6,%7}, {%8,%9}, {%0,%1,%2,%3};"
                            : "+f"(c1[mt][nt][0]), "+f"(c1[mt][nt][1]),
                              "+f"(c1[mt][nt][2]), "+f"(c1[mt][nt][3])
                            : "r"(af[mt][0]), "r"(af[mt][1]), "r"(af[mt][2]), "r"(af[mt][3]),
                              "r"(bf[nt][0]), "r"(bf[nt][1]));
            }
        }
        __syncthreads();  // all warps done reading sA

        // ====== phase 3: bias + SiLU; node->sHN(tf32), coord->dot partials ===
        if (w < 4) {
            #pragma unroll
            for (int mt = 0; mt < 4; mt++)
                #pragma unroll
                for (int nt = 0; nt < 4; nt++)
                    #pragma unroll
                    for (int r = 0; r < 4; r++) {
                        int row = (mt << 4) + lg + ((r >= 2) ? 8 : 0);
                        int col = (w << 5) + (nt << 3) + (lt << 1) + (r & 1);
                        float v = silu_f(c1[mt][nt][r] + bias1g[nt][r & 1]);
                        sHN[row * 132 + col] = f2t(v);
                    }
        } else {
            float part[4][2];
            #pragma unroll
            for (int mt = 0; mt < 4; mt++) { part[mt][0] = 0.0f; part[mt][1] = 0.0f; }
            #pragma unroll
            for (int mt = 0; mt < 4; mt++)
                #pragma unroll
                for (int nt = 0; nt < 4; nt++)
                    #pragma unroll
                    for (int r = 0; r < 4; r++) {
                        float v = silu_f(c1[mt][nt][r] + bias1g[nt][r & 1]);
                        part[mt][r >> 1] += v * wc2r[nt][r & 1];
                    }
            #pragma unroll
            for (int mt = 0; mt < 4; mt++)
                #pragma unroll
                for (int rh = 0; rh < 2; rh++) {
                    float p = part[mt][rh];
                    p += __shfl_xor_sync(0xffffffffu, p, 1);
                    p += __shfl_xor_sync(0xffffffffu, p, 2);
                    if (lt == 0) {
                        int row = (mt << 4) + lg + (rh << 3);
                        sP[row * 4 + (w - 4)] = p;
                    }
                }
        }
        __syncthreads();

        // ================= phase 4: GEMM2 (64x64x128, tf32) =================
        float c2[4][4];
        #pragma unroll
        for (int a = 0; a < 4; a++)
            #pragma unroll
            for (int r = 0; r < 4; r++) c2[a][r] = 0.0f;

        #pragma unroll 4
        for (int ks = 0; ks < 16; ks++) {
            int k0 = ks << 3;
            #pragma unroll
            for (int mt = 0; mt < 4; mt++) {
                int ba = ((mt << 4) + lg) * 132 + k0 + lt;
                uint32_t a0 = sHN[ba];
                uint32_t a1 = sHN[ba + 8 * 132];
                uint32_t a2 = sHN[ba + 4];
                uint32_t a3 = sHN[ba + 8 * 132 + 4];
                asm volatile(
                    "mma.sync.aligned.m16n8k8.row.col.f32.tf32.tf32.f32 "
                    "{%0,%1,%2,%3}, {%4,%5,%6,%7}, {%8,%9}, {%0,%1,%2,%3};"
                    : "+f"(c2[mt][0]), "+f"(c2[mt][1]), "+f"(c2[mt][2]), "+f"(c2[mt][3])
                    : "r"(a0), "r"(a1), "r"(a2), "r"(a3),
                      "r"(bw2[ks][0]), "r"(bw2[ks][1]));
            }
        }
        __syncthreads();  // sHN reads done before sM overwrites

        // ---- prefetch next tile's indices (covers ei/ed chain latency) ----
        pf_idx(t + gridDim.x);

        // ================= phase 5: stage m; coord epilogue =================
        #pragma unroll
        for (int mt = 0; mt < 4; mt++)
            #pragma unroll
            for (int r = 0; r < 4; r++) {
                int row = (mt << 4) + lg + ((r >= 2) ? 8 : 0);
                int col = (w << 3) + (lt << 1) + (r & 1);
                sM[row * 68 + col] = c2[mt][r] + ((r & 1) ? bn2g1 : bn2g0);
            }

        if (tid < TILE) {
            int m = tid;
            int dst = sDst[m];
            if (dst >= 0) {
                float cw = sP[m * 4] + sP[m * 4 + 1] + sP[m * 4 + 2] + sP[m * 4 + 3];
                int src = sSrc[m];
                float dx = x[src * 3]     - x[dst * 3];
                float dy = x[src * 3 + 1] - x[dst * 3 + 1];
                float dz = x[src * 3 + 2] - x[dst * 3 + 2];
                float len = sqrtf(dx * dx + dy * dy + dz * dz);
                len = fmaxf(len, 1e-8f);
                float s = cw / len;
                float* xo = outX + (size_t)dst * 3;
                asm volatile("red.global.add.f32 [%0], %1;" :: "l"(xo),     "f"(s * dx) : "memory");
                asm volatile("red.global.add.f32 [%0], %1;" :: "l"(xo + 1), "f"(s * dy) : "memory");
                asm volatile("red.global.add.f32 [%0], %1;" :: "l"(xo + 2), "f"(s * dz) : "memory");
            }
        }
        __syncthreads();  // sM visible to all

        // ================= phase 6: scatter h messages =================
        for (int i = tid; i < TILE * 16; i += NTHR) {
            int m = i >> 4, q = i & 15;
            int dst = sDst[m];
            if (dst >= 0) {
                float4 v = *(const float4*)(sM + m * 68 + (q << 2));
                float* ho = outH + (size_t)dst * ND + (q << 2);
                asm volatile("red.global.add.v4.f32 [%0], {%1,%2,%3,%4};"
                             :: "l"(ho), "f"(v.x), "f"(v.y), "f"(v.z), "f"(v.w) : "memory");
            }
        }
        __syncthreads();  // sM / sP reads done before next tile
    }
}

// ------------------------------------------------------------
extern "C" void kernel_launch(void* const* d_in, const int* in_sizes, int n_in,
                              void* d_out, int out_size)
{
    const float* h   = (const float*)d_in[0];
    const float* x   = (const float*)d_in[1];
    const int*   ei  = (const int*)d_in[2];      // int32 (JAX x64 disabled)
    const float* ed  = (const float*)d_in[3];
    const float* We1 = (const float*)d_in[4];
    const float* be1 = (const float*)d_in[5];
    const float* We2 = (const float*)d_in[6];
    const float* be2 = (const float*)d_in[7];
    const float* Wn1 = (const float*)d_in[8];
    const float* bn1 = (const float*)d_in[9];
    const float* Wn2 = (const float*)d_in[10];
    const float* bn2 = (const float*)d_in[11];
    const float* Wc1 = (const float*)d_in[12];
    const float* bc1 = (const float*)d_in[13];
    const float* Wc2 = (const float*)d_in[14];
    float* out = (float*)d_out;

    int E  = in_sizes[3];        // edge_dist element count
    int NN = in_sizes[0] / ND;   // nodes

    cudaFuncSetAttribute(egnn_fused, cudaFuncAttributeMaxDynamicSharedMemorySize, SMEM_TOTAL);

    egnn_fused<<<NCTAS, NTHR, SMEM_TOTAL>>>(h, x, ei, ed,
                                            We1, be1, We2, be2,
                                            Wn1, bn1, Wn2, bn2,
                                            Wc1, bc1, Wc2,
                                            out, E, NN);
}

// round 11
// speedup vs baseline: 1.6955x; 1.1147x over previous
#include <cuda_runtime.h>
#include <stdint.h>

// ============================================================
// EGNN layer — single fused persistent kernel, 512 threads/CTA.
//   out = [h + segsum(m, dst) | x + segsum(cw * dir/len, dst)]
// 16 warps: GEMM1 N-split 16x16cols, GEMM2 2x8 M/N-split.
// edge_index is int32. Coord columns get split-tf32 correction
// on the 32 edge K-rows.
// ============================================================

#define ND 64
#define ED 32
#define HD 128
#define K1 160   // 2*ND + ED
#define N1 256   // HD (node) + HD (coord)
#define TILE 64
#define ASTRIDE 196  // 160 hi + 32 s_lo + 4 pad
#define NCTAS 148
#define NTHR 512

__device__ unsigned gBar;   // zero-init; monotonic across graph replays

__device__ __forceinline__ uint32_t f2t(float x) {
    uint32_t r;
    asm("cvt.rna.tf32.f32 %0, %1;" : "=r"(r) : "f"(x));
    return r;
}
__device__ __forceinline__ float silu_f(float v) {
    return v / (1.0f + __expf(-v));
}

// ------------------------------------------------------------
// SMEM layout (bytes):
//   [0, 163840)        sW    : uint32[160*256] swizzled (n ^ ((k&3)<<3))
//   [163840, 180224)   sWlo  : uint32[32*128] swizzled (coord w_lo)
//   [180224, 230400)   union (phase-fenced by bar.sync):
//       A tile  uint32[64*196] (50176 B)        phases 1-2
//       sHidN   uint32[64*132] (33792 B)        phases 3-4
//       sP      float [64*8] @ +34816 (2048 B)  phases 3->5
//       sM      float [64*68]  (17408 B)        phases 5-6
//   [230400, 230656)   sEdge : We1[32] | be1[32]
//   [230656, 231168)   sSrc int[64], sDst int[64]
// ------------------------------------------------------------
#define SW_OFF    0
#define SWLO_OFF  163840
#define UN_OFF    180224
#define SP_OFF    (UN_OFF + 34816)
#define EDGE_OFF  230400
#define META_OFF  230656
#define SMEM_TOTAL 231168

__global__ void __launch_bounds__(NTHR, 1)
egnn_fused(const float* __restrict__ h, const float* __restrict__ x,
           const int* __restrict__ ei, const float* __restrict__ ed,
           const float* __restrict__ We1, const float* __restrict__ be1,
           const float* __restrict__ We2, const float* __restrict__ be2,
           const float* __restrict__ Wn1, const float* __restrict__ bn1,
           const float* __restrict__ Wn2, const float* __restrict__ bn2,
           const float* __restrict__ Wc1, const float* __restrict__ bc1,
           const float* __restrict__ Wc2,
           float* __restrict__ out, int E, int NN)
{
    extern __shared__ char smem[];
    uint32_t* sW   = (uint32_t*)(smem + SW_OFF);
    uint32_t* sWlo = (uint32_t*)(smem + SWLO_OFF);
    uint32_t* sA   = (uint32_t*)(smem + UN_OFF);
    uint32_t* sHN  = (uint32_t*)(smem + UN_OFF);
    float*    sM   = (float*)   (smem + UN_OFF);
    float*    sP   = (float*)   (smem + SP_OFF);
    float*    sEdg = (float*)   (smem + EDGE_OFF);
    int*      sSrc = (int*)     (smem + META_OFF);
    int*      sDst = (int*)     (smem + META_OFF + 256);

    const int tid = threadIdx.x;
    const int w  = tid >> 5;    // 0..15
    const int l  = tid & 31;
    const int lg = l >> 2;
    const int lt = l & 3;
    float* outH = out;
    float* outX = out + (size_t)NN * ND;

    // ================= init out = [h | x] (grid-strided) =================
    {
        const float4* h4 = (const float4*)h;
        float4* o4 = (float4*)out;
        int nh4 = NN * (ND / 4);
        for (int i = blockIdx.x * NTHR + tid; i < nh4; i += gridDim.x * NTHR)
            o4[i] = h4[i];
        int nx = NN * 3;
        for (int i = blockIdx.x * NTHR + tid; i < nx; i += gridDim.x * NTHR)
            outX[i] = x[i];
    }

    // ================= per-CTA weight fold into SMEM =================
    for (int idx = tid; idx < K1 * N1; idx += NTHR) {
        int k = idx >> 8, n = idx & 255;
        const float* W = (n < HD) ? Wn1 : Wc1;
        int nn = (n < HD) ? n : n - HD;
        float v;
        if (k < 2 * ND) {
            v = W[k * HD + nn];
        } else {
            int i = k - 2 * ND;
            float s = 0.0f;
            for (int j = 0; j < ED; j++)
                s += We2[i * ED + j] * W[(2 * ND + j) * HD + nn];
            v = s;
        }
        uint32_t hb = f2t(v);
        sW[k * N1 + (n ^ ((k & 3) << 3))] = hb;
        if (k >= 2 * ND && n >= HD) {
            int kk = k - 2 * ND, n2 = n - HD;
            sWlo[kk * HD + (n2 ^ ((kk & 3) << 3))] = f2t(v - __uint_as_float(hb));
        }
    }
    if (tid < ED)            sEdg[tid] = We1[tid];
    else if (tid < 2 * ED)   sEdg[tid] = be1[tid - ED];

    // ---- persistent register preloads ----
    uint32_t bw2[16][2];   // Wn2 B-fragments: warp (w&7) owns 8 N-cols
    #pragma unroll
    for (int ks = 0; ks < 16; ks++) {
        int kk = ks * 8 + lt;
        int nn = ((w & 7) << 3) + lg;
        bw2[ks][0] = f2t(Wn2[kk * ND + nn]);
        bw2[ks][1] = f2t(Wn2[(kk + 4) * ND + nn]);
    }
    float bias1g[2][2];   // fused bias (includes be2 fold), 16 cols/warp
    float wc2r[2][2];
    #pragma unroll
    for (int nt = 0; nt < 2; nt++) {
        #pragma unroll
        for (int j = 0; j < 2; j++) {
            int col = (w << 4) + (nt << 3) + (lt << 1) + j;
            const float* W; int nn; float s;
            if (col < HD) { s = bn1[col];      W = Wn1; nn = col; }
            else          { s = bc1[col - HD]; W = Wc1; nn = col - HD; }
            for (int jj = 0; jj < ED; jj++)
                s += be2[jj] * W[(2 * ND + jj) * HD + nn];
            bias1g[nt][j] = s;
            wc2r[nt][j] = (w >= 8) ? Wc2[col - HD] : 0.0f;
        }
    }
    float bn2g0 = bn2[((w & 7) << 3) + (lt << 1)];
    float bn2g1 = bn2[((w & 7) << 3) + (lt << 1) + 1];

    const int t8 = tid & 7;
    const int em = tid >> 3;       // edge-in-tile this thread serves in ph1

    // ================= grid barrier (monotonic epochs) =================
    __threadfence();
    __syncthreads();
    if (tid == 0) {
        unsigned ticket = atomicAdd(&gBar, 1u);
        unsigned target = (ticket / (unsigned)gridDim.x + 1u) * (unsigned)gridDim.x;
        unsigned v;
        do {
            asm volatile("ld.global.acquire.gpu.u32 %0, [%1];" : "=r"(v) : "l"(&gBar));
        } while (v < target);
    }
    __syncthreads();

    // ========= lightweight prefetch: indices + dist only =========
    int   pf_src = -1, pf_dst = -1;
    float pf_dist = 0.0f;

    auto pf_idx = [&](int tt) {
        int e = tt * TILE + em;
        pf_src = -1; pf_dst = -1;
        if (e < E) {
            pf_src  = ei[e];
            pf_dst  = ei[E + e];
            pf_dist = ed[e];
        }
    };

    const int nTiles = (E + TILE - 1) / TILE;
    int t = blockIdx.x;
    if (t < nTiles) pf_idx(t);

    for (; t < nTiles; t += gridDim.x) {
        // ================= phase 1: gather -> A tile (8 thr/edge) ==========
        {
            uint32_t* Arow = sA + em * ASTRIDE;
            if (pf_dst >= 0) {
                if (t8 == 0) { sSrc[em] = pf_src; sDst[em] = pf_dst; }
                const float4* rs = (const float4*)(h + (size_t)pf_src * ND);
                const float4* rd = (const float4*)(h + (size_t)pf_dst * ND);
                float4 vs0 = rs[t8];  float4 vs1 = rs[t8 + 8];
                float4 vd0 = rd[t8];  float4 vd1 = rd[t8 + 8];
                uint4 u;
                #define CVT_ST(v, off) \
                    u.x = f2t(v.x); u.y = f2t(v.y); u.z = f2t(v.z); u.w = f2t(v.w); \
                    *(uint4*)&Arow[off] = u;
                CVT_ST(vs0, (t8)      << 2)  CVT_ST(vs1, (t8 + 8)  << 2)
                CVT_ST(vd0, (t8 + 16) << 2)  CVT_ST(vd1, (t8 + 24) << 2)
                #undef CVT_ST
                {
                    int i0 = t8 << 2;
                    uint4 hi, lo;
                    float s;
                    s = silu_f(pf_dist * sEdg[i0]     + sEdg[ED + i0]);
                    hi.x = f2t(s); lo.x = f2t(s - __uint_as_float(hi.x));
                    s = silu_f(pf_dist * sEdg[i0 + 1] + sEdg[ED + i0 + 1]);
                    hi.y = f2t(s); lo.y = f2t(s - __uint_as_float(hi.y));
                    s = silu_f(pf_dist * sEdg[i0 + 2] + sEdg[ED + i0 + 2]);
                    hi.z = f2t(s); lo.z = f2t(s - __uint_as_float(hi.z));
                    s = silu_f(pf_dist * sEdg[i0 + 3] + sEdg[ED + i0 + 3]);
                    hi.w = f2t(s); lo.w = f2t(s - __uint_as_float(hi.w));
                    *(uint4*)&Arow[128 + i0] = hi;
                    *(uint4*)&Arow[160 + i0] = lo;
                }
            } else {
                if (t8 == 0) { sSrc[em] = 0; sDst[em] = -1; }
                uint4 z; z.x = z.y = z.z = z.w = 0;
                *(uint4*)&Arow[(t8)      << 2] = z;
                *(uint4*)&Arow[(t8 + 8)  << 2] = z;
                *(uint4*)&Arow[(t8 + 16) << 2] = z;
                *(uint4*)&Arow[(t8 + 24) << 2] = z;
                *(uint4*)&Arow[128 + (t8 << 2)] = z;
                *(uint4*)&Arow[160 + (t8 << 2)] = z;
            }
        }
        __syncthreads();

        // ========== phase 2: GEMM1 (64 x 16cols/warp x 160 + corr) ==========
        float c1[4][2][4];
        #pragma unroll
        for (int a = 0; a < 4; a++)
            #pragma unroll
            for (int b = 0; b < 2; b++)
                #pragma unroll
                for (int r = 0; r < 4; r++) c1[a][b][r] = 0.0f;

        const int sw = lt << 3;
        #pragma unroll 4
        for (int ks = 0; ks < 20; ks++) {
            int k0 = ks << 3;
            uint32_t af[4][4];
            #pragma unroll
            for (int mt = 0; mt < 4; mt++) {
                int ba = ((mt << 4) + lg) * ASTRIDE + k0 + lt;
                af[mt][0] = sA[ba];
                af[mt][1] = sA[ba + 8 * ASTRIDE];
                af[mt][2] = sA[ba + 4];
                af[mt][3] = sA[ba + 8 * ASTRIDE + 4];
            }
            uint32_t bf[2][2];
            int kb = (k0 + lt) * N1;
            #pragma unroll
            for (int nt = 0; nt < 2; nt++) {
                int cc = ((w << 4) + (nt << 3) + lg) ^ sw;
                bf[nt][0] = sW[kb + cc];
                bf[nt][1] = sW[kb + 4 * N1 + cc];
            }
            #pragma unroll
            for (int mt = 0; mt < 4; mt++)
                #pragma unroll
                for (int nt = 0; nt < 2; nt++)
                    asm volatile(
                        "mma.sync.aligned.m16n8k8.row.col.f32.tf32.tf32.f32 "
                        "{%0,%1,%2,%3}, {%4,%5,%6,%7}, {%8,%9}, {%0,%1,%2,%3};"
                        : "+f"(c1[mt][nt][0]), "+f"(c1[mt][nt][1]),
                          "+f"(c1[mt][nt][2]), "+f"(c1[mt][nt][3])
                        : "r"(af[mt][0]), "r"(af[mt][1]), "r"(af[mt][2]), "r"(af[mt][3]),
                          "r"(bf[nt][0]), "r"(bf[nt][1]));
        }

        if (w >= 8) {
            // correction 1: s_lo * w_hi ; correction 2: s_hi * w_lo
            #pragma unroll
            for (int pass = 0; pass < 2; pass++) {
                #pragma unroll
                for (int ks = 0; ks < 4; ks++) {
                    int k0a = (pass ? 128 : 160) + (ks << 3);
                    uint32_t af[4][4];
                    #pragma unroll
                    for (int mt = 0; mt < 4; mt++) {
                        int ba = ((mt << 4) + lg) * ASTRIDE + k0a + lt;
                        af[mt][0] = sA[ba];
                        af[mt][1] = sA[ba + 8 * ASTRIDE];
                        af[mt][2] = sA[ba + 4];
                        af[mt][3] = sA[ba + 8 * ASTRIDE + 4];
                    }
                    uint32_t bf[2][2];
                    if (pass == 0) {
                        int kb = (128 + (ks << 3) + lt) * N1;
                        #pragma unroll
                        for (int nt = 0; nt < 2; nt++) {
                            int cc = ((w << 4) + (nt << 3) + lg) ^ sw;
                            bf[nt][0] = sW[kb + cc];
                            bf[nt][1] = sW[kb + 4 * N1 + cc];
                        }
                    } else {
                        int kb = ((ks << 3) + lt) * HD;
                        #pragma unroll
                        for (int nt = 0; nt < 2; nt++) {
                            int cc = (((w - 8) << 4) + (nt << 3) + lg) ^ sw;
                            bf[nt][0] = sWlo[kb + cc];
                            bf[nt][1] = sWlo[kb + 4 * HD + cc];
                        }
                    }
                    #pragma unroll
                    for (int mt = 0; mt < 4; mt++)
                        #pragma unroll
                        for (int nt = 0; nt < 2; nt++)
                            asm volatile(
                                "mma.sync.aligned.m16n8k8.row.col.f32.tf32.tf32.f32 "
                                "{%0,%1,%2,%3}, {%4,%5,%6,%7}, {%8,%9}, {%0,%1,%2,%3};"
                                : "+f"(c1[mt][nt][0]), "+f"(c1[mt][nt][1]),
                                  "+f"(c1[mt][nt][2]), "+f"(c1[mt][nt][3])
                                : "r"(af[mt][0]), "r"(af[mt][1]), "r"(af[mt][2]), "r"(af[mt][3]),
                                  "r"(bf[nt][0]), "r"(bf[nt][1]));
                }
            }
        }
        __syncthreads();  // all warps done reading sA

        // ====== phase 3: bias + SiLU; node->sHN(tf32), coord->dot partials ===
        if (w < 8) {
            #pragma unroll
            for (int mt = 0; mt < 4; mt++)
                #pragma unroll
                for (int nt = 0; nt < 2; nt++)
                    #pragma unroll
                    for (int r = 0; r < 4; r++) {
                        int row = (mt << 4) + lg + ((r >= 2) ? 8 : 0);
                        int col = (w << 4) + (nt << 3) + (lt << 1) + (r & 1);
                        float v = silu_f(c1[mt][nt][r] + bias1g[nt][r & 1]);
                        sHN[row * 132 + col] = f2t(v);
                    }
        } else {
            float part[4][2];
            #pragma unroll
            for (int mt = 0; mt < 4; mt++) { part[mt][0] = 0.0f; part[mt][1] = 0.0f; }
            #pragma unroll
            for (int mt = 0; mt < 4; mt++)
                #pragma unroll
                for (int nt = 0; nt < 2; nt++)
                    #pragma unroll
                    for (int r = 0; r < 4; r++) {
                        float v = silu_f(c1[mt][nt][r] + bias1g[nt][r & 1]);
                        part[mt][r >> 1] += v * wc2r[nt][r & 1];
                    }
            #pragma unroll
            for (int mt = 0; mt < 4; mt++)
                #pragma unroll
                for (int rh = 0; rh < 2; rh++) {
                    float p = part[mt][rh];
                    p += __shfl_xor_sync(0xffffffffu, p, 1);
                    p += __shfl_xor_sync(0xffffffffu, p, 2);
                    if (lt == 0) {
                        int row = (mt << 4) + lg + (rh << 3);
                        sP[row * 8 + (w - 8)] = p;
                    }
                }
        }
        __syncthreads();

        // ====== phase 4: GEMM2 (M-split 2 x N-split 8 over 16 warps) =======
        float c2[2][4];
        #pragma unroll
        for (int a = 0; a < 2; a++)
            #pragma unroll
            for (int r = 0; r < 4; r++) c2[a][r] = 0.0f;

        const int mb = (w >> 3) << 5;   // 0 or 32
        #pragma unroll 4
        for (int ks = 0; ks < 16; ks++) {
            int k0 = ks << 3;
            #pragma unroll
            for (int mt = 0; mt < 2; mt++) {
                int ba = (mb + (mt << 4) + lg) * 132 + k0 + lt;
                uint32_t a0 = sHN[ba];
                uint32_t a1 = sHN[ba + 8 * 132];
                uint32_t a2 = sHN[ba + 4];
                uint32_t a3 = sHN[ba + 8 * 132 + 4];
                asm volatile(
                    "mma.sync.aligned.m16n8k8.row.col.f32.tf32.tf32.f32 "
                    "{%0,%1,%2,%3}, {%4,%5,%6,%7}, {%8,%9}, {%0,%1,%2,%3};"
                    : "+f"(c2[mt][0]), "+f"(c2[mt][1]), "+f"(c2[mt][2]), "+f"(c2[mt][3])
                    : "r"(a0), "r"(a1), "r"(a2), "r"(a3),
                      "r"(bw2[ks][0]), "r"(bw2[ks][1]));
            }
        }
        __syncthreads();  // sHN reads done before sM overwrites

        // ---- prefetch next tile's indices (covers ei/ed chain latency) ----
        pf_idx(t + gridDim.x);

        // ================= phase 5: stage m; coord epilogue =================
        #pragma unroll
        for (int mt = 0; mt < 2; mt++)
            #pragma unroll
            for (int r = 0; r < 4; r++) {
                int row = mb + (mt << 4) + lg + ((r >= 2) ? 8 : 0);
                int col = ((w & 7) << 3) + (lt << 1) + (r & 1);
                sM[row * 68 + col] = c2[mt][r] + ((r & 1) ? bn2g1 : bn2g0);
            }

        if (tid < TILE) {
            int m = tid;
            int dst = sDst[m];
            if (dst >= 0) {
                const float* pp = sP + m * 8;
                float cw = ((pp[0] + pp[1]) + (pp[2] + pp[3]))
                         + ((pp[4] + pp[5]) + (pp[6] + pp[7]));
                int src = sSrc[m];
                float dx = x[src * 3]     - x[dst * 3];
                float dy = x[src * 3 + 1] - x[dst * 3 + 1];
                float dz = x[src * 3 + 2] - x[dst * 3 + 2];
                float len = sqrtf(dx * dx + dy * dy + dz * dz);
                len = fmaxf(len, 1e-8f);
                float s = cw / len;
                float* xo = outX + (size_t)dst * 3;
                asm volatile("red.global.add.f32 [%0], %1;" :: "l"(xo),     "f"(s * dx) : "memory");
                asm volatile("red.global.add.f32 [%0], %1;" :: "l"(xo + 1), "f"(s * dy) : "memory");
                asm volatile("red.global.add.f32 [%0], %1;" :: "l"(xo + 2), "f"(s * dz) : "memory");
            }
        }
        __syncthreads();  // sM visible to all

        // ================= phase 6: scatter h messages =================
        for (int i = tid; i < TILE * 16; i += NTHR) {
            int m = i >> 4, q = i & 15;
            int dst = sDst[m];
            if (dst >= 0) {
                float4 v = *(const float4*)(sM + m * 68 + (q << 2));
                float* ho = outH + (size_t)dst * ND + (q << 2);
                asm volatile("red.global.add.v4.f32 [%0], {%1,%2,%3,%4};"
                             :: "l"(ho), "f"(v.x), "f"(v.y), "f"(v.z), "f"(v.w) : "memory");
            }
        }
        __syncthreads();  // sM / sP reads done before next tile
    }
}

// ------------------------------------------------------------
extern "C" void kernel_launch(void* const* d_in, const int* in_sizes, int n_in,
                              void* d_out, int out_size)
{
    const float* h   = (const float*)d_in[0];
    const float* x   = (const float*)d_in[1];
    const int*   ei  = (const int*)d_in[2];      // int32 (JAX x64 disabled)
    const float* ed  = (const float*)d_in[3];
    const float* We1 = (const float*)d_in[4];
    const float* be1 = (const float*)d_in[5];
    const float* We2 = (const float*)d_in[6];
    const float* be2 = (const float*)d_in[7];
    const float* Wn1 = (const float*)d_in[8];
    const float* bn1 = (const float*)d_in[9];
    const float* Wn2 = (const float*)d_in[10];
    const float* bn2 = (const float*)d_in[11];
    const float* Wc1 = (const float*)d_in[12];
    const float* bc1 = (const float*)d_in[13];
    const float* Wc2 = (const float*)d_in[14];
    float* out = (float*)d_out;

    int E  = in_sizes[3];        // edge_dist element count
    int NN = in_sizes[0] / ND;   // nodes

    cudaFuncSetAttribute(egnn_fused, cudaFuncAttributeMaxDynamicSharedMemorySize, SMEM_TOTAL);

    egnn_fused<<<NCTAS, NTHR, SMEM_TOTAL>>>(h, x, ei, ed,
                                            We1, be1, We2, be2,
                                            Wn1, bn1, Wn2, bn2,
                                            Wc1, bc1, Wc2,
                                            out, E, NN);
}

// round 14
// speedup vs baseline: 1.8328x; 1.0810x over previous
#include <cuda_runtime.h>
#include <stdint.h>

// ============================================================
// EGNN layer — single fused persistent kernel, 512 threads/CTA.
//   out = [h + segsum(m, dst) | x + segsum(cw * dir/len, dst)]
// GEMM1: 2x8 M/N warp split (LDS-byte balanced).
// GEMM2: 2x8 split, direct red.global.v2 epilogue (no sM stage).
// 4 barriers/tile. edge_index is int32. Coord columns get
// split-tf32 correction on the 32 edge K-rows.
// ============================================================

#define ND 64
#define ED 32
#define HD 128
#define K1 160   // 2*ND + ED
#define N1 256   // HD (node) + HD (coord)
#define TILE 64
#define ASTRIDE 196  // 160 hi + 32 s_lo + 4 pad
#define NCTAS 148
#define NTHR 512

__device__ unsigned gBar;   // zero-init; monotonic across graph replays

__device__ __forceinline__ uint32_t f2t(float x) {
    uint32_t r;
    asm("cvt.rna.tf32.f32 %0, %1;" : "=r"(r) : "f"(x));
    return r;
}
__device__ __forceinline__ float silu_f(float v) {
    return v / (1.0f + __expf(-v));
}

// ------------------------------------------------------------
// SMEM layout (bytes):
//   [0, 163840)        sW    : uint32[160*256] swizzled (n ^ ((k&3)<<3))
//   [163840, 180224)   sWlo  : uint32[32*128] swizzled (coord w_lo)
//   [180224, 230400)   union (phase-fenced by bar.sync):
//       A tile  uint32[64*196] (50176 B)   phases 1-2
//       sHidN   uint32[64*132] (33792 B)   phases 3-4
//   [230400, 231424)   sP    : float[64*4]  coord dot partials (ph3->epi)
//   [231424, 231680)   sEdge : We1[32] | be1[32]
//   [231680, 232192)   sSrc int[64], sDst int[64]
// ------------------------------------------------------------
#define SW_OFF    0
#define SWLO_OFF  163840
#define UN_OFF    180224
#define SP_OFF    230400
#define EDGE_OFF  231424
#define META_OFF  231680
#define SMEM_TOTAL 232192

__global__ void __launch_bounds__(NTHR, 1)
egnn_fused(const float* __restrict__ h, const float* __restrict__ x,
           const int* __restrict__ ei, const float* __restrict__ ed,
           const float* __restrict__ We1, const float* __restrict__ be1,
           const float* __restrict__ We2, const float* __restrict__ be2,
           const float* __restrict__ Wn1, const float* __restrict__ bn1,
           const float* __restrict__ Wn2, const float* __restrict__ bn2,
           const float* __restrict__ Wc1, const float* __restrict__ bc1,
           const float* __restrict__ Wc2,
           float* __restrict__ out, int E, int NN)
{
    extern __shared__ char smem[];
    uint32_t* sW   = (uint32_t*)(smem + SW_OFF);
    uint32_t* sWlo = (uint32_t*)(smem + SWLO_OFF);
    uint32_t* sA   = (uint32_t*)(smem + UN_OFF);
    uint32_t* sHN  = (uint32_t*)(smem + UN_OFF);
    float*    sP   = (float*)   (smem + SP_OFF);
    float*    sEdg = (float*)   (smem + EDGE_OFF);
    int*      sSrc = (int*)     (smem + META_OFF);
    int*      sDst = (int*)     (smem + META_OFF + 256);

    const int tid = threadIdx.x;
    const int w  = tid >> 5;    // 0..15
    const int l  = tid & 31;
    const int lg = l >> 2;
    const int lt = l & 3;
    const int wm = w >> 3;      // GEMM1 M-half (0,1)
    const int wn = w & 7;       // GEMM1 N-group (0..7), 32 cols each
    float* outH = out;
    float* outX = out + (size_t)NN * ND;

    // ================= init out = [h | x] (grid-strided) =================
    {
        const float4* h4 = (const float4*)h;
        float4* o4 = (float4*)out;
        int nh4 = NN * (ND / 4);
        for (int i = blockIdx.x * NTHR + tid; i < nh4; i += gridDim.x * NTHR)
            o4[i] = h4[i];
        int nx = NN * 3;
        for (int i = blockIdx.x * NTHR + tid; i < nx; i += gridDim.x * NTHR)
            outX[i] = x[i];
    }

    // ================= per-CTA weight fold into SMEM =================
    for (int idx = tid; idx < K1 * N1; idx += NTHR) {
        int k = idx >> 8, n = idx & 255;
        const float* W = (n < HD) ? Wn1 : Wc1;
        int nn = (n < HD) ? n : n - HD;
        float v;
        if (k < 2 * ND) {
            v = W[k * HD + nn];
        } else {
            int i = k - 2 * ND;
            float s = 0.0f;
            for (int j = 0; j < ED; j++)
                s += We2[i * ED + j] * W[(2 * ND + j) * HD + nn];
            v = s;
        }
        uint32_t hb = f2t(v);
        sW[k * N1 + (n ^ ((k & 3) << 3))] = hb;
        if (k >= 2 * ND && n >= HD) {
            int kk = k - 2 * ND, n2 = n - HD;
            sWlo[kk * HD + (n2 ^ ((kk & 3) << 3))] = f2t(v - __uint_as_float(hb));
        }
    }
    if (tid < ED)            sEdg[tid] = We1[tid];
    else if (tid < 2 * ED)   sEdg[tid] = be1[tid - ED];

    // ---- persistent register preloads ----
    uint32_t bw2[16][2];   // Wn2 B-fragments: warp wn owns 8 N-cols
    #pragma unroll
    for (int ks = 0; ks < 16; ks++) {
        int kk = ks * 8 + lt;
        int nn = (wn << 3) + lg;
        bw2[ks][0] = f2t(Wn2[kk * ND + nn]);
        bw2[ks][1] = f2t(Wn2[(kk + 4) * ND + nn]);
    }
    float bias1g[4][2];   // fused bias (includes be2 fold), 32 cols/warp
    float wc2r[4][2];
    #pragma unroll
    for (int nt = 0; nt < 4; nt++) {
        #pragma unroll
        for (int j = 0; j < 2; j++) {
            int col = (wn << 5) + (nt << 3) + (lt << 1) + j;
            const float* W; int nn; float s;
            if (col < HD) { s = bn1[col];      W = Wn1; nn = col; }
            else          { s = bc1[col - HD]; W = Wc1; nn = col - HD; }
            for (int jj = 0; jj < ED; jj++)
                s += be2[jj] * W[(2 * ND + jj) * HD + nn];
            bias1g[nt][j] = s;
            wc2r[nt][j] = (wn >= 4) ? Wc2[col - HD] : 0.0f;
        }
    }
    float bn2g0 = bn2[(wn << 3) + (lt << 1)];
    float bn2g1 = bn2[(wn << 3) + (lt << 1) + 1];

    const int t8 = tid & 7;
    const int em = tid >> 3;       // edge-in-tile this thread serves in ph1

    // ================= grid barrier (monotonic epochs) =================
    __threadfence();
    __syncthreads();
    if (tid == 0) {
        unsigned ticket = atomicAdd(&gBar, 1u);
        unsigned target = (ticket / (unsigned)gridDim.x + 1u) * (unsigned)gridDim.x;
        unsigned v;
        do {
            asm volatile("ld.global.acquire.gpu.u32 %0, [%1];" : "=r"(v) : "l"(&gBar));
        } while (v < target);
    }
    __syncthreads();

    // ========= lightweight prefetch: indices + dist only =========
    int   pf_src = -1, pf_dst = -1;
    float pf_dist = 0.0f;

    auto pf_idx = [&](int tt) {
        int e = tt * TILE + em;
        pf_src = -1; pf_dst = -1;
        if (e < E) {
            pf_src  = ei[e];
            pf_dst  = ei[E + e];
            pf_dist = ed[e];
        }
    };

    const int nTiles = (E + TILE - 1) / TILE;
    int t = blockIdx.x;
    if (t < nTiles) pf_idx(t);

    for (; t < nTiles; t += gridDim.x) {
        // ================= phase 1: gather -> A tile (8 thr/edge) ==========
        {
            uint32_t* Arow = sA + em * ASTRIDE;
            if (pf_dst >= 0) {
                if (t8 == 0) { sSrc[em] = pf_src; sDst[em] = pf_dst; }
                const float4* rs = (const float4*)(h + (size_t)pf_src * ND);
                const float4* rd = (const float4*)(h + (size_t)pf_dst * ND);
                float4 vs0 = rs[t8];  float4 vs1 = rs[t8 + 8];
                float4 vd0 = rd[t8];  float4 vd1 = rd[t8 + 8];
                uint4 u;
                #define CVT_ST(v, off) \
                    u.x = f2t(v.x); u.y = f2t(v.y); u.z = f2t(v.z); u.w = f2t(v.w); \
                    *(uint4*)&Arow[off] = u;
                CVT_ST(vs0, (t8)      << 2)  CVT_ST(vs1, (t8 + 8)  << 2)
                CVT_ST(vd0, (t8 + 16) << 2)  CVT_ST(vd1, (t8 + 24) << 2)
                #undef CVT_ST
                {
                    int i0 = t8 << 2;
                    uint4 hi, lo;
                    float s;
                    s = silu_f(pf_dist * sEdg[i0]     + sEdg[ED + i0]);
                    hi.x = f2t(s); lo.x = f2t(s - __uint_as_float(hi.x));
                    s = silu_f(pf_dist * sEdg[i0 + 1] + sEdg[ED + i0 + 1]);
                    hi.y = f2t(s); lo.y = f2t(s - __uint_as_float(hi.y));
                    s = silu_f(pf_dist * sEdg[i0 + 2] + sEdg[ED + i0 + 2]);
                    hi.z = f2t(s); lo.z = f2t(s - __uint_as_float(hi.z));
                    s = silu_f(pf_dist * sEdg[i0 + 3] + sEdg[ED + i0 + 3]);
                    hi.w = f2t(s); lo.w = f2t(s - __uint_as_float(hi.w));
                    *(uint4*)&Arow[128 + i0] = hi;
                    *(uint4*)&Arow[160 + i0] = lo;
                }
            } else {
                if (t8 == 0) { sSrc[em] = 0; sDst[em] = -1; }
                uint4 z; z.x = z.y = z.z = z.w = 0;
                *(uint4*)&Arow[(t8)      << 2] = z;
                *(uint4*)&Arow[(t8 + 8)  << 2] = z;
                *(uint4*)&Arow[(t8 + 16) << 2] = z;
                *(uint4*)&Arow[(t8 + 24) << 2] = z;
                *(uint4*)&Arow[128 + (t8 << 2)] = z;
                *(uint4*)&Arow[160 + (t8 << 2)] = z;
            }
        }
        __syncthreads();

        // ===== phase 2: GEMM1 (M-split 2 x N-split 8, 32x32 per warp) ======
        float c1[2][4][4];
        #pragma unroll
        for (int a = 0; a < 2; a++)
            #pragma unroll
            for (int b = 0; b < 4; b++)
                #pragma unroll
                for (int r = 0; r < 4; r++) c1[a][b][r] = 0.0f;

        const int sw = lt << 3;
        const int mbase = wm << 5;   // 0 or 32
        #pragma unroll 4
        for (int ks = 0; ks < 20; ks++) {
            int k0 = ks << 3;
            uint32_t af[2][4];
            #pragma unroll
            for (int mt = 0; mt < 2; mt++) {
                int ba = (mbase + (mt << 4) + lg) * ASTRIDE + k0 + lt;
                af[mt][0] = sA[ba];
                af[mt][1] = sA[ba + 8 * ASTRIDE];
                af[mt][2] = sA[ba + 4];
                af[mt][3] = sA[ba + 8 * ASTRIDE + 4];
            }
            uint32_t bf[4][2];
            int kb = (k0 + lt) * N1;
            #pragma unroll
            for (int nt = 0; nt < 4; nt++) {
                int cc = ((wn << 5) + (nt << 3) + lg) ^ sw;
                bf[nt][0] = sW[kb + cc];
                bf[nt][1] = sW[kb + 4 * N1 + cc];
            }
            #pragma unroll
            for (int mt = 0; mt < 2; mt++)
                #pragma unroll
                for (int nt = 0; nt < 4; nt++)
                    asm volatile(
                        "mma.sync.aligned.m16n8k8.row.col.f32.tf32.tf32.f32 "
                        "{%0,%1,%2,%3}, {%4,%5,%6,%7}, {%8,%9}, {%0,%1,%2,%3};"
                        : "+f"(c1[mt][nt][0]), "+f"(c1[mt][nt][1]),
                          "+f"(c1[mt][nt][2]), "+f"(c1[mt][nt][3])
                        : "r"(af[mt][0]), "r"(af[mt][1]), "r"(af[mt][2]), "r"(af[mt][3]),
                          "r"(bf[nt][0]), "r"(bf[nt][1]));
        }

        if (wn >= 4) {
            // corrections on coord cols: pass0 s_lo*w_hi, pass1 s_hi*w_lo
            #pragma unroll
            for (int pass = 0; pass < 2; pass++) {
                #pragma unroll
                for (int ks = 0; ks < 4; ks++) {
                    int k0a = (pass ? 128 : 160) + (ks << 3);
                    uint32_t af[2][4];
                    #pragma unroll
                    for (int mt = 0; mt < 2; mt++) {
                        int ba = (mbase + (mt << 4) + lg) * ASTRIDE + k0a + lt;
                        af[mt][0] = sA[ba];
                        af[mt][1] = sA[ba + 8 * ASTRIDE];
                        af[mt][2] = sA[ba + 4];
                        af[mt][3] = sA[ba + 8 * ASTRIDE + 4];
                    }
                    uint32_t bf[4][2];
                    if (pass == 0) {
                        int kb = (128 + (ks << 3) + lt) * N1;
                        #pragma unroll
                        for (int nt = 0; nt < 4; nt++) {
                            int cc = ((wn << 5) + (nt << 3) + lg) ^ sw;
                            bf[nt][0] = sW[kb + cc];
                            bf[nt][1] = sW[kb + 4 * N1 + cc];
                        }
                    } else {
                        int kb = ((ks << 3) + lt) * HD;
                        #pragma unroll
                        for (int nt = 0; nt < 4; nt++) {
                            int cc = (((wn - 4) << 5) + (nt << 3) + lg) ^ sw;
                            bf[nt][0] = sWlo[kb + cc];
                            bf[nt][1] = sWlo[kb + 4 * HD + cc];
                        }
                    }
                    #pragma unroll
                    for (int mt = 0; mt < 2; mt++)
                        #pragma unroll
                        for (int nt = 0; nt < 4; nt++)
                            asm volatile(
                                "mma.sync.aligned.m16n8k8.row.col.f32.tf32.tf32.f32 "
                                "{%0,%1,%2,%3}, {%4,%5,%6,%7}, {%8,%9}, {%0,%1,%2,%3};"
                                : "+f"(c1[mt][nt][0]), "+f"(c1[mt][nt][1]),
                                  "+f"(c1[mt][nt][2]), "+f"(c1[mt][nt][3])
                                : "r"(af[mt][0]), "r"(af[mt][1]), "r"(af[mt][2]), "r"(af[mt][3]),
                                  "r"(bf[nt][0]), "r"(bf[nt][1]));
                }
            }
        }
        __syncthreads();  // all warps done reading sA

        // ====== phase 3: bias + SiLU; node->sHN(tf32), coord->dot partials ===
        if (wn < 4) {
            #pragma unroll
            for (int mt = 0; mt < 2; mt++)
                #pragma unroll
                for (int nt = 0; nt < 4; nt++)
                    #pragma unroll
                    for (int rh = 0; rh < 2; rh++) {
                        int row = mbase + (mt << 4) + lg + (rh << 3);
                        int col = (wn << 5) + (nt << 3) + (lt << 1);
                        float v0 = silu_f(c1[mt][nt][rh << 1]       + bias1g[nt][0]);
                        float v1 = silu_f(c1[mt][nt][(rh << 1) + 1] + bias1g[nt][1]);
                        uint32_t u0 = f2t(v0), u1 = f2t(v1);
                        uint64_t pk = (uint64_t)u0 | ((uint64_t)u1 << 32);
                        *(uint64_t*)&sHN[row * 132 + col] = pk;
                    }
        } else {
            float part[2][2];
            #pragma unroll
            for (int mt = 0; mt < 2; mt++) { part[mt][0] = 0.0f; part[mt][1] = 0.0f; }
            #pragma unroll
            for (int mt = 0; mt < 2; mt++)
                #pragma unroll
                for (int nt = 0; nt < 4; nt++)
                    #pragma unroll
                    for (int r = 0; r < 4; r++) {
                        float v = silu_f(c1[mt][nt][r] + bias1g[nt][r & 1]);
                        part[mt][r >> 1] += v * wc2r[nt][r & 1];
                    }
            #pragma unroll
            for (int mt = 0; mt < 2; mt++)
                #pragma unroll
                for (int rh = 0; rh < 2; rh++) {
                    float p = part[mt][rh];
                    p += __shfl_xor_sync(0xffffffffu, p, 1);
                    p += __shfl_xor_sync(0xffffffffu, p, 2);
                    if (lt == 0) {
                        int row = mbase + (mt << 4) + lg + (rh << 3);
                        sP[row * 4 + (wn - 4)] = p;
                    }
                }
        }
        __syncthreads();

        // ====== phase 4: GEMM2 (M-split 2 x N-split 8 over 16 warps) =======
        float c2[2][4];
        #pragma unroll
        for (int a = 0; a < 2; a++)
            #pragma unroll
            for (int r = 0; r < 4; r++) c2[a][r] = 0.0f;

        #pragma unroll 4
        for (int ks = 0; ks < 16; ks++) {
            int k0 = ks << 3;
            #pragma unroll
            for (int mt = 0; mt < 2; mt++) {
                int ba = (mbase + (mt << 4) + lg) * 132 + k0 + lt;
                uint32_t a0 = sHN[ba];
                uint32_t a1 = sHN[ba + 8 * 132];
                uint32_t a2 = sHN[ba + 4];
                uint32_t a3 = sHN[ba + 8 * 132 + 4];
                asm volatile(
                    "mma.sync.aligned.m16n8k8.row.col.f32.tf32.tf32.f32 "
                    "{%0,%1,%2,%3}, {%4,%5,%6,%7}, {%8,%9}, {%0,%1,%2,%3};"
                    : "+f"(c2[mt][0]), "+f"(c2[mt][1]), "+f"(c2[mt][2]), "+f"(c2[mt][3])
                    : "r"(a0), "r"(a1), "r"(a2), "r"(a3),
                      "r"(bw2[ks][0]), "r"(bw2[ks][1]));
            }
        }

        // ---- prefetch next tile's indices (covers ei/ed chain latency) ----
        pf_idx(t + gridDim.x);

        // ====== epilogue: direct red.v2 scatter of h-messages ======
        #pragma unroll
        for (int mt = 0; mt < 2; mt++)
            #pragma unroll
            for (int rh = 0; rh < 2; rh++) {
                int row = mbase + (mt << 4) + lg + (rh << 3);
                int dst = sDst[row];
                if (dst >= 0) {
                    float v0 = c2[mt][rh << 1]       + bn2g0;
                    float v1 = c2[mt][(rh << 1) + 1] + bn2g1;
                    float* ho = outH + (size_t)dst * ND + (wn << 3) + (lt << 1);
                    asm volatile("red.global.add.v2.f32 [%0], {%1,%2};"
                                 :: "l"(ho), "f"(v0), "f"(v1) : "memory");
                }
            }

        // ====== coord epilogue (reads sP; before barrier) ======
        if (tid < TILE) {
            int m = tid;
            int dst = sDst[m];
            if (dst >= 0) {
                const float* pp = sP + m * 4;
                float cw = (pp[0] + pp[1]) + (pp[2] + pp[3]);
                int src = sSrc[m];
                float dx = x[src * 3]     - x[dst * 3];
                float dy = x[src * 3 + 1] - x[dst * 3 + 1];
                float dz = x[src * 3 + 2] - x[dst * 3 + 2];
                float len = sqrtf(dx * dx + dy * dy + dz * dz);
                len = fmaxf(len, 1e-8f);
                float s = cw / len;
                float* xo = outX + (size_t)dst * 3;
                asm volatile("red.global.add.f32 [%0], %1;" :: "l"(xo),     "f"(s * dx) : "memory");
                asm volatile("red.global.add.f32 [%0], %1;" :: "l"(xo + 1), "f"(s * dy) : "memory");
                asm volatile("red.global.add.f32 [%0], %1;" :: "l"(xo + 2), "f"(s * dz) : "memory");
            }
        }
        __syncthreads();  // sHN/sP/sDst reads done before next tile's writes
    }
}

// ------------------------------------------------------------
extern "C" void kernel_launch(void* const* d_in, const int* in_sizes, int n_in,
                              void* d_out, int out_size)
{
    const float* h   = (const float*)d_in[0];
    const float* x   = (const float*)d_in[1];
    const int*   ei  = (const int*)d_in[2];      // int32 (JAX x64 disabled)
    const float* ed  = (const float*)d_in[3];
    const float* We1 = (const float*)d_in[4];
    const float* be1 = (const float*)d_in[5];
    const float* We2 = (const float*)d_in[6];
    const float* be2 = (const float*)d_in[7];
    const float* Wn1 = (const float*)d_in[8];
    const float* bn1 = (const float*)d_in[9];
    const float* Wn2 = (const float*)d_in[10];
    const float* bn2 = (const float*)d_in[11];
    const float* Wc1 = (const float*)d_in[12];
    const float* bc1 = (const float*)d_in[13];
    const float* Wc2 = (const float*)d_in[14];
    float* out = (float*)d_out;

    int E  = in_sizes[3];        // edge_dist element count
    int NN = in_sizes[0] / ND;   // nodes

    cudaFuncSetAttribute(egnn_fused, cudaFuncAttributeMaxDynamicSharedMemorySize, SMEM_TOTAL);

    egnn_fused<<<NCTAS, NTHR, SMEM_TOTAL>>>(h, x, ei, ed,
                                            We1, be1, We2, be2,
                                            Wn1, bn1, Wn2, bn2,
                                            Wc1, bc1, Wc2,
                                            out, E, NN);
}

// round 17
// speedup vs baseline: 1.8878x; 1.0300x over previous
#include <cuda_runtime.h>
#include <stdint.h>

// ============================================================
// EGNN layer — single fused persistent kernel, 512 thr/CTA,
// TWO independent 256-thread groups on 32-edge tiles (named
// barriers). Groups drift out of phase -> tensor/memory overlap.
// GEMM1: N-split 8 per group. GEMM2: 8-col split, direct red.v2
// epilogue. edge_index int32. Split-tf32 correction on the 32
// edge K-rows for coord columns.
// NOTE: tcgen05 unavailable — harness ptxas target is sm_103
// (no 'a' suffix); arch-specific features rejected.
// ============================================================

#define ND 64
#define ED 32
#define HD 128
#define K1 160   // 2*ND + ED
#define N1 256   // HD (node) + HD (coord)
#define TILE 32  // edges per group-tile
#define ASTRIDE 196  // 160 hi + 32 s_lo + 4 pad
#define UN_STRIDE 25088  // 32*196*4 bytes per group union
#define NCTAS 148
#define NTHR 512

__device__ unsigned gBar;   // zero-init; monotonic across graph replays

__device__ __forceinline__ uint32_t f2t(float x) {
    uint32_t r;
    asm("cvt.rna.tf32.f32 %0, %1;" : "=r"(r) : "f"(x));
    return r;
}
__device__ __forceinline__ float silu_f(float v) {
    return v / (1.0f + __expf(-v));
}
__device__ __forceinline__ void gbar(int id) {
    asm volatile("bar.sync %0, 256;" :: "r"(id) : "memory");
}

// ------------------------------------------------------------
// SMEM layout (bytes):
//   [0, 163840)        sW    : uint32[160*256] swizzled (n ^ ((k&3)<<3))
//   [163840, 180224)   sWlo  : uint32[32*128] swizzled (coord w_lo)
//   [180224, 230400)   2 x group union (25088 B each, phase-fenced):
//       A tile  uint32[32*196]   phases 1-2
//       sHidN   uint32[32*132]   phases 3-4
//   [230400, 231424)   sP    : float[2][32*4] coord dot partials
//   [231424, 231680)   sEdge : We1[32] | be1[32]
//   [231680, 232192)   sSrc int[2][32], sDst int[2][32]
// ------------------------------------------------------------
#define SW_OFF    0
#define SWLO_OFF  163840
#define UN_OFF    180224
#define SP_OFF    230400
#define EDGE_OFF  231424
#define META_OFF  231680
#define SMEM_TOTAL 232192

__global__ void __launch_bounds__(NTHR, 1)
egnn_fused(const float* __restrict__ h, const float* __restrict__ x,
           const int* __restrict__ ei, const float* __restrict__ ed,
           const float* __restrict__ We1, const float* __restrict__ be1,
           const float* __restrict__ We2, const float* __restrict__ be2,
           const float* __restrict__ Wn1, const float* __restrict__ bn1,
           const float* __restrict__ Wn2, const float* __restrict__ bn2,
           const float* __restrict__ Wc1, const float* __restrict__ bc1,
           const float* __restrict__ Wc2,
           float* __restrict__ out, int E, int NN)
{
    extern __shared__ char smem[];
    uint32_t* sW   = (uint32_t*)(smem + SW_OFF);
    uint32_t* sWlo = (uint32_t*)(smem + SWLO_OFF);
    float*    sEdg = (float*)   (smem + EDGE_OFF);

    const int tid = threadIdx.x;
    const int g   = tid >> 8;          // group 0/1
    const int tl  = tid & 255;         // thread-in-group
    const int wl  = tl >> 5;           // warp-in-group 0..7
    const int l   = tid & 31;
    const int lg  = l >> 2;
    const int lt  = l & 3;

    uint32_t* sA   = (uint32_t*)(smem + UN_OFF + g * UN_STRIDE);
    uint32_t* sHN  = sA;
    float*    sP   = (float*)(smem + SP_OFF) + g * 128;
    int*      sSrc = (int*)(smem + META_OFF) + g * TILE;
    int*      sDst = (int*)(smem + META_OFF + 256) + g * TILE;
    const int bid  = 1 + g;            // named barrier id

    float* outH = out;
    float* outX = out + (size_t)NN * ND;

    // ================= init out = [h | x] (grid-strided) =================
    {
        const float4* h4 = (const float4*)h;
        float4* o4 = (float4*)out;
        int nh4 = NN * (ND / 4);
        for (int i = blockIdx.x * NTHR + tid; i < nh4; i += gridDim.x * NTHR)
            o4[i] = h4[i];
        int nx = NN * 3;
        for (int i = blockIdx.x * NTHR + tid; i < nx; i += gridDim.x * NTHR)
            outX[i] = x[i];
    }

    // ================= per-CTA weight fold into SMEM =================
    for (int idx = tid; idx < K1 * N1; idx += NTHR) {
        int k = idx >> 8, n = idx & 255;
        const float* W = (n < HD) ? Wn1 : Wc1;
        int nn = (n < HD) ? n : n - HD;
        float v;
        if (k < 2 * ND) {
            v = W[k * HD + nn];
        } else {
            int i = k - 2 * ND;
            float s = 0.0f;
            for (int j = 0; j < ED; j++)
                s += We2[i * ED + j] * W[(2 * ND + j) * HD + nn];
            v = s;
        }
        uint32_t hb = f2t(v);
        sW[k * N1 + (n ^ ((k & 3) << 3))] = hb;
        if (k >= 2 * ND && n >= HD) {
            int kk = k - 2 * ND, n2 = n - HD;
            sWlo[kk * HD + (n2 ^ ((kk & 3) << 3))] = f2t(v - __uint_as_float(hb));
        }
    }
    if (tid < ED)            sEdg[tid] = We1[tid];
    else if (tid < 2 * ED)   sEdg[tid] = be1[tid - ED];

    // ---- persistent register preloads (group-local warp index wl) ----
    uint32_t bw2[16][2];   // Wn2 B-fragments: warp wl owns 8 N-cols
    #pragma unroll
    for (int ks = 0; ks < 16; ks++) {
        int kk = ks * 8 + lt;
        int nn = (wl << 3) + lg;
        bw2[ks][0] = f2t(Wn2[kk * ND + nn]);
        bw2[ks][1] = f2t(Wn2[(kk + 4) * ND + nn]);
    }
    float bias1g[4][2];   // fused bias (includes be2 fold), 32 cols/warp
    float wc2r[4][2];
    #pragma unroll
    for (int nt = 0; nt < 4; nt++) {
        #pragma unroll
        for (int j = 0; j < 2; j++) {
            int col = (wl << 5) + (nt << 3) + (lt << 1) + j;
            const float* W; int nn; float s;
            if (col < HD) { s = bn1[col];      W = Wn1; nn = col; }
            else          { s = bc1[col - HD]; W = Wc1; nn = col - HD; }
            for (int jj = 0; jj < ED; jj++)
                s += be2[jj] * W[(2 * ND + jj) * HD + nn];
            bias1g[nt][j] = s;
            wc2r[nt][j] = (wl >= 4) ? Wc2[col - HD] : 0.0f;
        }
    }
    float bn2g0 = bn2[(wl << 3) + (lt << 1)];
    float bn2g1 = bn2[(wl << 3) + (lt << 1) + 1];

    const int t8 = tid & 7;
    const int em = (tid >> 3) & 31;    // edge-in-tile this thread serves

    // ================= grid barrier (monotonic epochs) =================
    __threadfence();
    __syncthreads();
    if (tid == 0) {
        unsigned ticket = atomicAdd(&gBar, 1u);
        unsigned target = (ticket / (unsigned)gridDim.x + 1u) * (unsigned)gridDim.x;
        unsigned v;
        do {
            asm volatile("ld.global.acquire.gpu.u32 %0, [%1];" : "=r"(v) : "l"(&gBar));
        } while (v < target);
    }
    __syncthreads();

    // ========= lightweight prefetch: indices + dist only =========
    int   pf_src = -1, pf_dst = -1;
    float pf_dist = 0.0f;

    auto pf_idx = [&](int tt) {
        int e = tt * TILE + em;
        pf_src = -1; pf_dst = -1;
        if (e < E) {
            pf_src  = ei[e];
            pf_dst  = ei[E + e];
            pf_dist = ed[e];
        }
    };

    const int nTiles = (E + TILE - 1) / TILE;
    const int tstep = gridDim.x * 2;
    int t = blockIdx.x * 2 + g;
    if (t < nTiles) pf_idx(t);

    for (; t < nTiles; t += tstep) {
        // ================= phase 1: gather -> A tile (8 thr/edge) ==========
        {
            uint32_t* Arow = sA + em * ASTRIDE;
            if (pf_dst >= 0) {
                if (t8 == 0) { sSrc[em] = pf_src; sDst[em] = pf_dst; }
                const float4* rs = (const float4*)(h + (size_t)pf_src * ND);
                const float4* rd = (const float4*)(h + (size_t)pf_dst * ND);
                float4 vs0 = rs[t8];  float4 vs1 = rs[t8 + 8];
                float4 vd0 = rd[t8];  float4 vd1 = rd[t8 + 8];
                uint4 u;
                #define CVT_ST(v, off) \
                    u.x = f2t(v.x); u.y = f2t(v.y); u.z = f2t(v.z); u.w = f2t(v.w); \
                    *(uint4*)&Arow[off] = u;
                CVT_ST(vs0, (t8)      << 2)  CVT_ST(vs1, (t8 + 8)  << 2)
                CVT_ST(vd0, (t8 + 16) << 2)  CVT_ST(vd1, (t8 + 24) << 2)
                #undef CVT_ST
                {
                    int i0 = t8 << 2;
                    uint4 hi, lo;
                    float s;
                    s = silu_f(pf_dist * sEdg[i0]     + sEdg[ED + i0]);
                    hi.x = f2t(s); lo.x = f2t(s - __uint_as_float(hi.x));
                    s = silu_f(pf_dist * sEdg[i0 + 1] + sEdg[ED + i0 + 1]);
                    hi.y = f2t(s); lo.y = f2t(s - __uint_as_float(hi.y));
                    s = silu_f(pf_dist * sEdg[i0 + 2] + sEdg[ED + i0 + 2]);
                    hi.z = f2t(s); lo.z = f2t(s - __uint_as_float(hi.z));
                    s = silu_f(pf_dist * sEdg[i0 + 3] + sEdg[ED + i0 + 3]);
                    hi.w = f2t(s); lo.w = f2t(s - __uint_as_float(hi.w));
                    *(uint4*)&Arow[128 + i0] = hi;
                    *(uint4*)&Arow[160 + i0] = lo;
                }
            } else {
                if (t8 == 0) { sSrc[em] = 0; sDst[em] = -1; }
                uint4 z; z.x = z.y = z.z = z.w = 0;
                *(uint4*)&Arow[(t8)      << 2] = z;
                *(uint4*)&Arow[(t8 + 8)  << 2] = z;
                *(uint4*)&Arow[(t8 + 16) << 2] = z;
                *(uint4*)&Arow[(t8 + 24) << 2] = z;
                *(uint4*)&Arow[128 + (t8 << 2)] = z;
                *(uint4*)&Arow[160 + (t8 << 2)] = z;
            }
        }
        gbar(bid);

        // ===== phase 2: GEMM1 (32 rows x 32 cols/warp, N-split 8) ==========
        float c1[2][4][4];
        #pragma unroll
        for (int a = 0; a < 2; a++)
            #pragma unroll
            for (int b = 0; b < 4; b++)
                #pragma unroll
                for (int r = 0; r < 4; r++) c1[a][b][r] = 0.0f;

        const int sw = lt << 3;
        #pragma unroll 4
        for (int ks = 0; ks < 20; ks++) {
            int k0 = ks << 3;
            uint32_t af[2][4];
            #pragma unroll
            for (int mt = 0; mt < 2; mt++) {
                int ba = ((mt << 4) + lg) * ASTRIDE + k0 + lt;
                af[mt][0] = sA[ba];
                af[mt][1] = sA[ba + 8 * ASTRIDE];
                af[mt][2] = sA[ba + 4];
                af[mt][3] = sA[ba + 8 * ASTRIDE + 4];
            }
            uint32_t bf[4][2];
            int kb = (k0 + lt) * N1;
            #pragma unroll
            for (int nt = 0; nt < 4; nt++) {
                int cc = ((wl << 5) + (nt << 3) + lg) ^ sw;
                bf[nt][0] = sW[kb + cc];
                bf[nt][1] = sW[kb + 4 * N1 + cc];
            }
            #pragma unroll
            for (int mt = 0; mt < 2; mt++)
                #pragma unroll
                for (int nt = 0; nt < 4; nt++)
                    asm volatile(
                        "mma.sync.aligned.m16n8k8.row.col.f32.tf32.tf32.f32 "
                        "{%0,%1,%2,%3}, {%4,%5,%6,%7}, {%8,%9}, {%0,%1,%2,%3};"
                        : "+f"(c1[mt][nt][0]), "+f"(c1[mt][nt][1]),
                          "+f"(c1[mt][nt][2]), "+f"(c1[mt][nt][3])
                        : "r"(af[mt][0]), "r"(af[mt][1]), "r"(af[mt][2]), "r"(af[mt][3]),
                          "r"(bf[nt][0]), "r"(bf[nt][1]));
        }

        if (wl >= 4) {
            // corrections on coord cols: pass0 s_lo*w_hi, pass1 s_hi*w_lo
            #pragma unroll
            for (int pass = 0; pass < 2; pass++) {
                #pragma unroll
                for (int ks = 0; ks < 4; ks++) {
                    int k0a = (pass ? 128 : 160) + (ks << 3);
                    uint32_t af[2][4];
                    #pragma unroll
                    for (int mt = 0; mt < 2; mt++) {
                        int ba = ((mt << 4) + lg) * ASTRIDE + k0a + lt;
                        af[mt][0] = sA[ba];
                        af[mt][1] = sA[ba + 8 * ASTRIDE];
                        af[mt][2] = sA[ba + 4];
                        af[mt][3] = sA[ba + 8 * ASTRIDE + 4];
                    }
                    uint32_t bf[4][2];
                    if (pass == 0) {
                        int kb = (128 + (ks << 3) + lt) * N1;
                        #pragma unroll
                        for (int nt = 0; nt < 4; nt++) {
                            int cc = ((wl << 5) + (nt << 3) + lg) ^ sw;
                            bf[nt][0] = sW[kb + cc];
                            bf[nt][1] = sW[kb + 4 * N1 + cc];
                        }
                    } else {
                        int kb = ((ks << 3) + lt) * HD;
                        #pragma unroll
                        for (int nt = 0; nt < 4; nt++) {
                            int cc = (((wl - 4) << 5) + (nt << 3) + lg) ^ sw;
                            bf[nt][0] = sWlo[kb + cc];
                            bf[nt][1] = sWlo[kb + 4 * HD + cc];
                        }
                    }
                    #pragma unroll
                    for (int mt = 0; mt < 2; mt++)
                        #pragma unroll
                        for (int nt = 0; nt < 4; nt++)
                            asm volatile(
                                "mma.sync.aligned.m16n8k8.row.col.f32.tf32.tf32.f32 "
                                "{%0,%1,%2,%3}, {%4,%5,%6,%7}, {%8,%9}, {%0,%1,%2,%3};"
                                : "+f"(c1[mt][nt][0]), "+f"(c1[mt][nt][1]),
                                  "+f"(c1[mt][nt][2]), "+f"(c1[mt][nt][3])
                                : "r"(af[mt][0]), "r"(af[mt][1]), "r"(af[mt][2]), "r"(af[mt][3]),
                                  "r"(bf[nt][0]), "r"(bf[nt][1]));
                }
            }
        }
        gbar(bid);  // all group warps done reading sA

        // ====== phase 3: bias + SiLU; node->sHN(tf32), coord->dot partials ===
        if (wl < 4) {
            #pragma unroll
            for (int mt = 0; mt < 2; mt++)
                #pragma unroll
                for (int nt = 0; nt < 4; nt++)
                    #pragma unroll
                    for (int rh = 0; rh < 2; rh++) {
                        int row = (mt << 4) + lg + (rh << 3);
                        int col = (wl << 5) + (nt << 3) + (lt << 1);
                        float v0 = silu_f(c1[mt][nt][rh << 1]       + bias1g[nt][0]);
                        float v1 = silu_f(c1[mt][nt][(rh << 1) + 1] + bias1g[nt][1]);
                        uint32_t u0 = f2t(v0), u1 = f2t(v1);
                        uint64_t pk = (uint64_t)u0 | ((uint64_t)u1 << 32);
                        *(uint64_t*)&sHN[row * 132 + col] = pk;
                    }
        } else {
            float part[2][2];
            #pragma unroll
            for (int mt = 0; mt < 2; mt++) { part[mt][0] = 0.0f; part[mt][1] = 0.0f; }
            #pragma unroll
            for (int mt = 0; mt < 2; mt++)
                #pragma unroll
                for (int nt = 0; nt < 4; nt++)
                    #pragma unroll
                    for (int r = 0; r < 4; r++) {
                        float v = silu_f(c1[mt][nt][r] + bias1g[nt][r & 1]);
                        part[mt][r >> 1] += v * wc2r[nt][r & 1];
                    }
            #pragma unroll
            for (int mt = 0; mt < 2; mt++)
                #pragma unroll
                for (int rh = 0; rh < 2; rh++) {
                    float p = part[mt][rh];
                    p += __shfl_xor_sync(0xffffffffu, p, 1);
                    p += __shfl_xor_sync(0xffffffffu, p, 2);
                    if (lt == 0) {
                        int row = (mt << 4) + lg + (rh << 3);
                        sP[row * 4 + (wl - 4)] = p;
                    }
                }
        }
        gbar(bid);

        // ====== phase 4: GEMM2 (32 rows, 8 cols/warp) ======
        float c2[2][4];
        #pragma unroll
        for (int a = 0; a < 2; a++)
            #pragma unroll
            for (int r = 0; r < 4; r++) c2[a][r] = 0.0f;

        #pragma unroll 4
        for (int ks = 0; ks < 16; ks++) {
            int k0 = ks << 3;
            #pragma unroll
            for (int mt = 0; mt < 2; mt++) {
                int ba = ((mt << 4) + lg) * 132 + k0 + lt;
                uint32_t a0 = sHN[ba];
                uint32_t a1 = sHN[ba + 8 * 132];
                uint32_t a2 = sHN[ba + 4];
                uint32_t a3 = sHN[ba + 8 * 132 + 4];
                asm volatile(
                    "mma.sync.aligned.m16n8k8.row.col.f32.tf32.tf32.f32 "
                    "{%0,%1,%2,%3}, {%4,%5,%6,%7}, {%8,%9}, {%0,%1,%2,%3};"
                    : "+f"(c2[mt][0]), "+f"(c2[mt][1]), "+f"(c2[mt][2]), "+f"(c2[mt][3])
                    : "r"(a0), "r"(a1), "r"(a2), "r"(a3),
                      "r"(bw2[ks][0]), "r"(bw2[ks][1]));
            }
        }

        // ---- prefetch next tile's indices (covers ei/ed chain latency) ----
        pf_idx(t + tstep);

        // ====== epilogue: direct red.v2 scatter of h-messages ======
        #pragma unroll
        for (int mt = 0; mt < 2; mt++)
            #pragma unroll
            for (int rh = 0; rh < 2; rh++) {
                int row = (mt << 4) + lg + (rh << 3);
                int dst = sDst[row];
                if (dst >= 0) {
                    float v0 = c2[mt][rh << 1]       + bn2g0;
                    float v1 = c2[mt][(rh << 1) + 1] + bn2g1;
                    float* ho = outH + (size_t)dst * ND + (wl << 3) + (lt << 1);
                    asm volatile("red.global.add.v2.f32 [%0], {%1,%2};"
                                 :: "l"(ho), "f"(v0), "f"(v1) : "memory");
                }
            }

        // ====== coord epilogue (reads sP; before barrier) ======
        if (tl < TILE) {
            int m = tl;
            int dst = sDst[m];
            if (dst >= 0) {
                const float* pp = sP + m * 4;
                float cw = (pp[0] + pp[1]) + (pp[2] + pp[3]);
                int src = sSrc[m];
                float dx = x[src * 3]     - x[dst * 3];
                float dy = x[src * 3 + 1] - x[dst * 3 + 1];
                float dz = x[src * 3 + 2] - x[dst * 3 + 2];
                float len = sqrtf(dx * dx + dy * dy + dz * dz);
                len = fmaxf(len, 1e-8f);
                float s = cw / len;
                float* xo = outX + (size_t)dst * 3;
                asm volatile("red.global.add.f32 [%0], %1;" :: "l"(xo),     "f"(s * dx) : "memory");
                asm volatile("red.global.add.f32 [%0], %1;" :: "l"(xo + 1), "f"(s * dy) : "memory");
                asm volatile("red.global.add.f32 [%0], %1;" :: "l"(xo + 2), "f"(s * dz) : "memory");
            }
        }
        gbar(bid);  // sHN/sP/sDst reads done before next tile's writes
    }
}

// ------------------------------------------------------------
extern "C" void kernel_launch(void* const* d_in, const int* in_sizes, int n_in,
                              void* d_out, int out_size)
{
    const float* h   = (const float*)d_in[0];
    const float* x   = (const float*)d_in[1];
    const int*   ei  = (const int*)d_in[2];      // int32 (JAX x64 disabled)
    const float* ed  = (const float*)d_in[3];
    const float* We1 = (const float*)d_in[4];
    const float* be1 = (const float*)d_in[5];
    const float* We2 = (const float*)d_in[6];
    const float* be2 = (const float*)d_in[7];
    const float* Wn1 = (const float*)d_in[8];
    const float* bn1 = (const float*)d_in[9];
    const float* Wn2 = (const float*)d_in[10];
    const float* bn2 = (const float*)d_in[11];
    const float* Wc1 = (const float*)d_in[12];
    const float* bc1 = (const float*)d_in[13];
    const float* Wc2 = (const float*)d_in[14];
    float* out = (float*)d_out;

    int E  = in_sizes[3];        // edge_dist element count
    int NN = in_sizes[0] / ND;   // nodes

    cudaFuncSetAttribute(egnn_fused, cudaFuncAttributeMaxDynamicSharedMemorySize, SMEM_TOTAL);

    egnn_fused<<<NCTAS, NTHR, SMEM_TOTAL>>>(h, x, ei, ed,
                                            We1, be1, We2, be2,
                                            Wn1, bn1, Wn2, bn2,
                                            Wc1, bc1, Wc2,
                                            out, E, NN);
}